// round 1
// baseline (speedup 1.0000x reference)
#include <cuda_runtime.h>
#include <cuda_bf16.h>
#include <cstdint>

#define NN 50000
#define EE 800000
#define DD 128
#define HH 8
#define CC 16
#define LL 4

// ---------------- device scratch (static: allocation-free rule) ----------------
__device__ float g_q[NN * DD];
__device__ float g_k[NN * DD];
__device__ float g_v[NN * DD];
__device__ float g_s[NN * DD];
__device__ float g_x0[NN * DD];
__device__ float g_x1[NN * DD];
__device__ int   g_cnt[NN];
__device__ int   g_off[NN + 1];
__device__ int   g_cur[NN];
__device__ int   g_src[EE];
__device__ int   g_part[64];

// ---------------- CSR build ----------------
__global__ void k_zero_cnt() {
    int i = blockIdx.x * blockDim.x + threadIdx.x;
    if (i < NN) g_cnt[i] = 0;
}

__global__ void k_hist(const int* __restrict__ dst) {
    int e = blockIdx.x * blockDim.x + threadIdx.x;
    if (e < EE) atomicAdd(&g_cnt[dst[e]], 1);
}

// block-wise Hillis-Steele scan, 1024/block
__global__ void k_scan1() {
    __shared__ int sm[1024];
    int tid = threadIdx.x;
    int i = blockIdx.x * 1024 + tid;
    int vin = (i < NN) ? g_cnt[i] : 0;
    sm[tid] = vin;
    __syncthreads();
#pragma unroll
    for (int o = 1; o < 1024; o <<= 1) {
        int t = (tid >= o) ? sm[tid - o] : 0;
        __syncthreads();
        sm[tid] += t;
        __syncthreads();
    }
    if (i < NN) g_off[i] = sm[tid] - vin;     // block-local exclusive
    if (tid == 1023) g_part[blockIdx.x] = sm[1023];
}

__global__ void k_scan2(int nb) {
    __shared__ int sm[64];
    int tid = threadIdx.x;     // 64 threads
    int v = (tid < nb) ? g_part[tid] : 0;
    sm[tid] = v;
    __syncthreads();
#pragma unroll
    for (int o = 1; o < 64; o <<= 1) {
        int t = (tid >= o) ? sm[tid - o] : 0;
        __syncthreads();
        sm[tid] += t;
        __syncthreads();
    }
    if (tid < nb) g_part[tid] = sm[tid] - v;  // exclusive block prefix
}

__global__ void k_scan3() {
    int i = blockIdx.x * 1024 + threadIdx.x;
    if (i < NN) {
        int o = g_off[i] + g_part[blockIdx.x];
        g_off[i] = o;
        g_cur[i] = o;
    }
    if (i == 0) g_off[NN] = EE;
}

__global__ void k_scatter(const int* __restrict__ src, const int* __restrict__ dst) {
    int e = blockIdx.x * blockDim.x + threadIdx.x;
    if (e < EE) {
        int d = dst[e];
        int p = atomicAdd(&g_cur[d], 1);
        g_src[p] = src[e];
    }
}

// ---------------- fp32 GEMM: out[M,128] = A[M,128] @ W[128,128] + bias ----------------
// block: 256 threads, 64 rows x 128 cols per block, k-chunk 32
__global__ void gemm128(const float* __restrict__ A, const float* __restrict__ W,
                        const float* __restrict__ bias, float* __restrict__ out, int M) {
    __shared__ float As[64][33];
    __shared__ float Ws[32][128];
    int tid = threadIdx.x;
    int tx = tid & 15;        // output col group: cols tx*8..tx*8+7
    int ty = tid >> 4;        // output row group: rows ty*4..ty*4+3
    int rowBase = blockIdx.x * 64;

    float acc[4][8];
#pragma unroll
    for (int i = 0; i < 4; i++)
#pragma unroll
        for (int j = 0; j < 8; j++) acc[i][j] = 0.f;

    int lr = tid >> 2;          // A-load row 0..63
    int lk = (tid & 3) * 8;     // A-load k offset 0,8,16,24
    int wr = tid >> 3;          // W-load k row 0..31
    int wc = (tid & 7) * 16;    // W-load col 0..112
    bool rowOk = (rowBase + lr) < M;

    for (int k0 = 0; k0 < 128; k0 += 32) {
        float4 a0 = {0,0,0,0}, a1 = {0,0,0,0};
        if (rowOk) {
            const float4* ap = (const float4*)(A + (size_t)(rowBase + lr) * 128 + k0 + lk);
            a0 = ap[0]; a1 = ap[1];
        }
        const float4* wp = (const float4*)(W + (size_t)(k0 + wr) * 128 + wc);
        float4 w0 = wp[0], w1 = wp[1], w2 = wp[2], w3 = wp[3];
        __syncthreads();
        As[lr][lk + 0] = a0.x; As[lr][lk + 1] = a0.y; As[lr][lk + 2] = a0.z; As[lr][lk + 3] = a0.w;
        As[lr][lk + 4] = a1.x; As[lr][lk + 5] = a1.y; As[lr][lk + 6] = a1.z; As[lr][lk + 7] = a1.w;
        *(float4*)&Ws[wr][wc + 0]  = w0;
        *(float4*)&Ws[wr][wc + 4]  = w1;
        *(float4*)&Ws[wr][wc + 8]  = w2;
        *(float4*)&Ws[wr][wc + 12] = w3;
        __syncthreads();
#pragma unroll
        for (int kk = 0; kk < 32; kk++) {
            float a0_ = As[ty * 4 + 0][kk];
            float a1_ = As[ty * 4 + 1][kk];
            float a2_ = As[ty * 4 + 2][kk];
            float a3_ = As[ty * 4 + 3][kk];
            float4 b0 = *(const float4*)&Ws[kk][tx * 8];
            float4 b1 = *(const float4*)&Ws[kk][tx * 8 + 4];
            acc[0][0] += a0_ * b0.x; acc[0][1] += a0_ * b0.y; acc[0][2] += a0_ * b0.z; acc[0][3] += a0_ * b0.w;
            acc[0][4] += a0_ * b1.x; acc[0][5] += a0_ * b1.y; acc[0][6] += a0_ * b1.z; acc[0][7] += a0_ * b1.w;
            acc[1][0] += a1_ * b0.x; acc[1][1] += a1_ * b0.y; acc[1][2] += a1_ * b0.z; acc[1][3] += a1_ * b0.w;
            acc[1][4] += a1_ * b1.x; acc[1][5] += a1_ * b1.y; acc[1][6] += a1_ * b1.z; acc[1][7] += a1_ * b1.w;
            acc[2][0] += a2_ * b0.x; acc[2][1] += a2_ * b0.y; acc[2][2] += a2_ * b0.z; acc[2][3] += a2_ * b0.w;
            acc[2][4] += a2_ * b1.x; acc[2][5] += a2_ * b1.y; acc[2][6] += a2_ * b1.z; acc[2][7] += a2_ * b1.w;
            acc[3][0] += a3_ * b0.x; acc[3][1] += a3_ * b0.y; acc[3][2] += a3_ * b0.z; acc[3][3] += a3_ * b0.w;
            acc[3][4] += a3_ * b1.x; acc[3][5] += a3_ * b1.y; acc[3][6] += a3_ * b1.z; acc[3][7] += a3_ * b1.w;
        }
    }

    float4 bb0 = *(const float4*)(bias + tx * 8);
    float4 bb1 = *(const float4*)(bias + tx * 8 + 4);
#pragma unroll
    for (int i = 0; i < 4; i++) {
        int row = rowBase + ty * 4 + i;
        if (row < M) {
            float4 o0, o1;
            o0.x = acc[i][0] + bb0.x; o0.y = acc[i][1] + bb0.y;
            o0.z = acc[i][2] + bb0.z; o0.w = acc[i][3] + bb0.w;
            o1.x = acc[i][4] + bb1.x; o1.y = acc[i][5] + bb1.y;
            o1.z = acc[i][6] + bb1.z; o1.w = acc[i][7] + bb1.w;
            *(float4*)(out + (size_t)row * 128 + tx * 8)     = o0;
            *(float4*)(out + (size_t)row * 128 + tx * 8 + 4) = o1;
        }
    }
}

// ---------------- attention: warp per dst node, online softmax over incoming edges ----------------
// lane = head*4 + c4 ; each lane owns 4 channels (float4) of its head
__global__ void attn(const float* __restrict__ q, const float* __restrict__ k,
                     const float* __restrict__ v, const float* __restrict__ skip,
                     float* __restrict__ out) {
    int warp = (blockIdx.x * blockDim.x + threadIdx.x) >> 5;
    if (warp >= NN) return;
    int lane = threadIdx.x & 31;
    int col  = (lane >> 2) * 16 + (lane & 3) * 4;   // head*16 + chunk*4

    float4 q4 = *(const float4*)(q + (size_t)warp * 128 + col);
    float m = -1e30f, z = 0.f;
    float4 acc = {0.f, 0.f, 0.f, 0.f};

    int beg = g_off[warp], end = g_off[warp + 1];
    for (int base = beg; base < end; base += 32) {
        int mye = base + lane;
        int sreg = (mye < end) ? g_src[mye] : 0;
        int cnt = min(32, end - base);
        for (int i = 0; i < cnt; i++) {
            int sn = __shfl_sync(0xffffffffu, sreg, i);
            const float4 k4 = *(const float4*)(k + (size_t)sn * 128 + col);
            float d = q4.x * k4.x + q4.y * k4.y + q4.z * k4.z + q4.w * k4.w;
            d += __shfl_xor_sync(0xffffffffu, d, 1);
            d += __shfl_xor_sync(0xffffffffu, d, 2);
            d *= 0.25f;   // 1/sqrt(16)
            const float4 v4 = *(const float4*)(v + (size_t)sn * 128 + col);
            if (d > m) {
                float sc = __expf(m - d);
                z *= sc; acc.x *= sc; acc.y *= sc; acc.z *= sc; acc.w *= sc;
                m = d;
            }
            float p = __expf(d - m);
            z += p;
            acc.x += p * v4.x; acc.y += p * v4.y; acc.z += p * v4.z; acc.w += p * v4.w;
        }
    }

    float inv = (z > 0.f) ? 1.f / z : 0.f;
    float4 sk = *(const float4*)(skip + (size_t)warp * 128 + col);
    float4 o;
    o.x = fmaxf(acc.x * inv + sk.x, 0.f);
    o.y = fmaxf(acc.y * inv + sk.y, 0.f);
    o.z = fmaxf(acc.z * inv + sk.z, 0.f);
    o.w = fmaxf(acc.w * inv + sk.w, 0.f);
    *(float4*)(out + (size_t)warp * 128 + col) = o;
}

// ---------------- launch ----------------
extern "C" void kernel_launch(void* const* d_in, const int* in_sizes, int n_in,
                              void* d_out, int out_size) {
    const float* x    = (const float*)d_in[0];
    const int*   ei   = (const int*)d_in[1];
    const float* Wq   = (const float*)d_in[3];
    const float* bq   = (const float*)d_in[4];
    const float* Wk   = (const float*)d_in[5];
    const float* bk   = (const float*)d_in[6];
    const float* Wv   = (const float*)d_in[7];
    const float* bv   = (const float*)d_in[8];
    const float* Wsk  = (const float*)d_in[9];
    const float* bsk  = (const float*)d_in[10];
    const float* Wout = (const float*)d_in[11];
    const float* bout = (const float*)d_in[12];

    const int* srcv = ei;        // edge_index[0]
    const int* dstv = ei + EE;   // edge_index[1]

    float *pq, *pk, *pv, *ps, *px0, *px1;
    cudaGetSymbolAddress((void**)&pq,  g_q);
    cudaGetSymbolAddress((void**)&pk,  g_k);
    cudaGetSymbolAddress((void**)&pv,  g_v);
    cudaGetSymbolAddress((void**)&ps,  g_s);
    cudaGetSymbolAddress((void**)&px0, g_x0);
    cudaGetSymbolAddress((void**)&px1, g_x1);

    // ---- CSR build ----
    k_zero_cnt<<<(NN + 255) / 256, 256>>>();
    k_hist<<<(EE + 255) / 256, 256>>>(dstv);
    int nb = (NN + 1023) / 1024;   // 49
    k_scan1<<<nb, 1024>>>();
    k_scan2<<<1, 64>>>(nb);
    k_scan3<<<nb, 1024>>>();
    k_scatter<<<(EE + 255) / 256, 256>>>(srcv, dstv);

    // ---- layers ----
    int gemmBlocks = (NN + 63) / 64;
    int attnBlocks = (NN + 7) / 8;     // 8 warps / block
    const float* xin = x;
    float* bufs[2] = {px0, px1};
    for (int l = 0; l < LL; l++) {
        const float* wq = Wq + (size_t)l * 128 * 128;
        const float* wk = Wk + (size_t)l * 128 * 128;
        const float* wv = Wv + (size_t)l * 128 * 128;
        const float* ws = Wsk + (size_t)l * 128 * 128;
        gemm128<<<gemmBlocks, 256>>>(xin, wq, bq + l * 128, pq, NN);
        gemm128<<<gemmBlocks, 256>>>(xin, wk, bk + l * 128, pk, NN);
        gemm128<<<gemmBlocks, 256>>>(xin, wv, bv + l * 128, pv, NN);
        gemm128<<<gemmBlocks, 256>>>(xin, ws, bsk + l * 128, ps, NN);
        float* xo = bufs[l & 1];
        attn<<<attnBlocks, 256>>>(pq, pk, pv, ps, xo);
        xin = xo;
    }

    // ---- final linear ----
    gemm128<<<gemmBlocks, 256>>>(xin, Wout, bout, (float*)d_out, NN);
}

// round 2
// speedup vs baseline: 1.3458x; 1.3458x over previous
#include <cuda_runtime.h>
#include <cuda_bf16.h>
#include <cstdint>

#define NN 50000
#define EE 800000
#define DD 128
#define HH 8
#define CC 16
#define LL 4

// ---------------- device scratch (static: allocation-free rule) ----------------
__device__ float g_q[NN * DD];
__device__ float g_k[NN * DD];
__device__ float g_v[NN * DD];
__device__ float g_s[NN * DD];
__device__ float g_x0[NN * DD];
__device__ float g_x1[NN * DD];
__device__ int   g_cnt[NN];
__device__ int   g_off[NN + 1];
__device__ int   g_cur[NN];
__device__ int   g_src[EE];
__device__ int   g_part[64];

// ---------------- CSR build ----------------
__global__ void k_zero_cnt() {
    int i = blockIdx.x * blockDim.x + threadIdx.x;
    if (i < NN) g_cnt[i] = 0;
}

__global__ void k_hist(const int* __restrict__ dst) {
    int e = blockIdx.x * blockDim.x + threadIdx.x;
    if (e < EE) atomicAdd(&g_cnt[dst[e]], 1);
}

__global__ void k_scan1() {
    __shared__ int sm[1024];
    int tid = threadIdx.x;
    int i = blockIdx.x * 1024 + tid;
    int vin = (i < NN) ? g_cnt[i] : 0;
    sm[tid] = vin;
    __syncthreads();
#pragma unroll
    for (int o = 1; o < 1024; o <<= 1) {
        int t = (tid >= o) ? sm[tid - o] : 0;
        __syncthreads();
        sm[tid] += t;
        __syncthreads();
    }
    if (i < NN) g_off[i] = sm[tid] - vin;
    if (tid == 1023) g_part[blockIdx.x] = sm[1023];
}

__global__ void k_scan2(int nb) {
    __shared__ int sm[64];
    int tid = threadIdx.x;
    int v = (tid < nb) ? g_part[tid] : 0;
    sm[tid] = v;
    __syncthreads();
#pragma unroll
    for (int o = 1; o < 64; o <<= 1) {
        int t = (tid >= o) ? sm[tid - o] : 0;
        __syncthreads();
        sm[tid] += t;
        __syncthreads();
    }
    if (tid < nb) g_part[tid] = sm[tid] - v;
}

__global__ void k_scan3() {
    int i = blockIdx.x * 1024 + threadIdx.x;
    if (i < NN) {
        int o = g_off[i] + g_part[blockIdx.x];
        g_off[i] = o;
        g_cur[i] = o;
    }
    if (i == 0) g_off[NN] = EE;
}

__global__ void k_scatter(const int* __restrict__ src, const int* __restrict__ dst) {
    int e = blockIdx.x * blockDim.x + threadIdx.x;
    if (e < EE) {
        int d = dst[e];
        int p = atomicAdd(&g_cur[d], 1);
        g_src[p] = src[e];
    }
}

// ---------------- fused SGEMM: up to 4 matrices, 128x128 block, 8x8/thread ----------------
// gridDim.x = row tiles, gridDim.y = matrix index (selects W/bias/out)
__global__ void __launch_bounds__(256, 2)
gemmQKVS(const float* __restrict__ A,
         const float* __restrict__ W0, const float* __restrict__ W1,
         const float* __restrict__ W2, const float* __restrict__ W3,
         const float* __restrict__ b0, const float* __restrict__ b1,
         const float* __restrict__ b2, const float* __restrict__ b3,
         float* __restrict__ o0, float* __restrict__ o1,
         float* __restrict__ o2, float* __restrict__ o3, int M) {
    const float* W; const float* bias; float* out;
    switch (blockIdx.y) {
        case 0: W = W0; bias = b0; out = o0; break;
        case 1: W = W1; bias = b1; out = o1; break;
        case 2: W = W2; bias = b2; out = o2; break;
        default: W = W3; bias = b3; out = o3; break;
    }

    __shared__ float As[2][16][128];   // [k][m]
    __shared__ float Bs[2][16][128];   // [k][n]

    int tid = threadIdx.x;
    int tc = tid & 15;          // col group: cols tc*8..tc*8+7
    int tr = tid >> 4;          // row group: rows tr*8..tr*8+7
    int m0 = blockIdx.x * 128;

    // global-load mapping
    int lrow = tid >> 2;            // A: 0..63 (+64 for second half)
    int lk4  = (tid & 3) * 4;       // A: k offset 0,4,8,12
    int wkr  = tid >> 5;            // B: k row 0..7 (+8 second half)
    int wnc  = (tid & 31) * 4;      // B: col 0..124

    float acc[8][8];
#pragma unroll
    for (int i = 0; i < 8; i++)
#pragma unroll
        for (int j = 0; j < 8; j++) acc[i][j] = 0.f;

    bool r0ok = (m0 + lrow) < M;
    bool r1ok = (m0 + lrow + 64) < M;

    // prologue: load chunk 0 into buffer 0
    float4 sa0 = {0,0,0,0}, sa1 = {0,0,0,0};
    if (r0ok) sa0 = *(const float4*)(A + (size_t)(m0 + lrow) * 128 + lk4);
    if (r1ok) sa1 = *(const float4*)(A + (size_t)(m0 + lrow + 64) * 128 + lk4);
    float4 sw0 = *(const float4*)(W + (size_t)wkr * 128 + wnc);
    float4 sw1 = *(const float4*)(W + (size_t)(wkr + 8) * 128 + wnc);
    As[0][lk4 + 0][lrow] = sa0.x; As[0][lk4 + 1][lrow] = sa0.y;
    As[0][lk4 + 2][lrow] = sa0.z; As[0][lk4 + 3][lrow] = sa0.w;
    As[0][lk4 + 0][lrow + 64] = sa1.x; As[0][lk4 + 1][lrow + 64] = sa1.y;
    As[0][lk4 + 2][lrow + 64] = sa1.z; As[0][lk4 + 3][lrow + 64] = sa1.w;
    *(float4*)&Bs[0][wkr][wnc] = sw0;
    *(float4*)&Bs[0][wkr + 8][wnc] = sw1;
    __syncthreads();

#pragma unroll
    for (int kc = 0; kc < 8; kc++) {
        int cur = kc & 1;
        // stage next chunk into registers (latency hidden by compute below)
        if (kc < 7) {
            int k0 = (kc + 1) * 16;
            sa0 = make_float4(0,0,0,0); sa1 = make_float4(0,0,0,0);
            if (r0ok) sa0 = *(const float4*)(A + (size_t)(m0 + lrow) * 128 + k0 + lk4);
            if (r1ok) sa1 = *(const float4*)(A + (size_t)(m0 + lrow + 64) * 128 + k0 + lk4);
            sw0 = *(const float4*)(W + (size_t)(k0 + wkr) * 128 + wnc);
            sw1 = *(const float4*)(W + (size_t)(k0 + wkr + 8) * 128 + wnc);
        }
#pragma unroll
        for (int kk = 0; kk < 16; kk++) {
            float4 a0 = *(const float4*)&As[cur][kk][tr * 8];
            float4 a1 = *(const float4*)&As[cur][kk][tr * 8 + 4];
            float4 b0 = *(const float4*)&Bs[cur][kk][tc * 8];
            float4 b1 = *(const float4*)&Bs[cur][kk][tc * 8 + 4];
            float ar[8] = {a0.x, a0.y, a0.z, a0.w, a1.x, a1.y, a1.z, a1.w};
            float br[8] = {b0.x, b0.y, b0.z, b0.w, b1.x, b1.y, b1.z, b1.w};
#pragma unroll
            for (int i = 0; i < 8; i++)
#pragma unroll
                for (int j = 0; j < 8; j++)
                    acc[i][j] += ar[i] * br[j];
        }
        if (kc < 7) {
            int nxt = cur ^ 1;
            As[nxt][lk4 + 0][lrow] = sa0.x; As[nxt][lk4 + 1][lrow] = sa0.y;
            As[nxt][lk4 + 2][lrow] = sa0.z; As[nxt][lk4 + 3][lrow] = sa0.w;
            As[nxt][lk4 + 0][lrow + 64] = sa1.x; As[nxt][lk4 + 1][lrow + 64] = sa1.y;
            As[nxt][lk4 + 2][lrow + 64] = sa1.z; As[nxt][lk4 + 3][lrow + 64] = sa1.w;
            *(float4*)&Bs[nxt][wkr][wnc] = sw0;
            *(float4*)&Bs[nxt][wkr + 8][wnc] = sw1;
            __syncthreads();
        }
    }

    float4 bb0 = *(const float4*)(bias + tc * 8);
    float4 bb1 = *(const float4*)(bias + tc * 8 + 4);
#pragma unroll
    for (int i = 0; i < 8; i++) {
        int row = m0 + tr * 8 + i;
        if (row < M) {
            float4 u0, u1;
            u0.x = acc[i][0] + bb0.x; u0.y = acc[i][1] + bb0.y;
            u0.z = acc[i][2] + bb0.z; u0.w = acc[i][3] + bb0.w;
            u1.x = acc[i][4] + bb1.x; u1.y = acc[i][5] + bb1.y;
            u1.z = acc[i][6] + bb1.z; u1.w = acc[i][7] + bb1.w;
            *(float4*)(out + (size_t)row * 128 + tc * 8)     = u0;
            *(float4*)(out + (size_t)row * 128 + tc * 8 + 4) = u1;
        }
    }
}

// ---------------- attention: warp per dst node, online softmax ----------------
__global__ void attn(const float* __restrict__ q, const float* __restrict__ k,
                     const float* __restrict__ v, const float* __restrict__ skip,
                     float* __restrict__ out) {
    int warp = (blockIdx.x * blockDim.x + threadIdx.x) >> 5;
    if (warp >= NN) return;
    int lane = threadIdx.x & 31;
    int col  = (lane >> 2) * 16 + (lane & 3) * 4;   // head*16 + chunk*4

    float4 q4 = *(const float4*)(q + (size_t)warp * 128 + col);
    float m = -1e30f, z = 0.f;
    float4 acc = {0.f, 0.f, 0.f, 0.f};

    int beg = g_off[warp], end = g_off[warp + 1];
    for (int base = beg; base < end; base += 32) {
        int mye = base + lane;
        int sreg = (mye < end) ? g_src[mye] : 0;
        int cnt = min(32, end - base);
        for (int i = 0; i < cnt; i++) {
            int sn = __shfl_sync(0xffffffffu, sreg, i);
            const float4 k4 = *(const float4*)(k + (size_t)sn * 128 + col);
            float d = q4.x * k4.x + q4.y * k4.y + q4.z * k4.z + q4.w * k4.w;
            d += __shfl_xor_sync(0xffffffffu, d, 1);
            d += __shfl_xor_sync(0xffffffffu, d, 2);
            d *= 0.25f;   // 1/sqrt(16)
            const float4 v4 = *(const float4*)(v + (size_t)sn * 128 + col);
            if (d > m) {
                float sc = __expf(m - d);
                z *= sc; acc.x *= sc; acc.y *= sc; acc.z *= sc; acc.w *= sc;
                m = d;
            }
            float p = __expf(d - m);
            z += p;
            acc.x += p * v4.x; acc.y += p * v4.y; acc.z += p * v4.z; acc.w += p * v4.w;
        }
    }

    float inv = (z > 0.f) ? 1.f / z : 0.f;
    float4 sk = *(const float4*)(skip + (size_t)warp * 128 + col);
    float4 o;
    o.x = fmaxf(acc.x * inv + sk.x, 0.f);
    o.y = fmaxf(acc.y * inv + sk.y, 0.f);
    o.z = fmaxf(acc.z * inv + sk.z, 0.f);
    o.w = fmaxf(acc.w * inv + sk.w, 0.f);
    *(float4*)(out + (size_t)warp * 128 + col) = o;
}

// ---------------- launch ----------------
extern "C" void kernel_launch(void* const* d_in, const int* in_sizes, int n_in,
                              void* d_out, int out_size) {
    const float* x    = (const float*)d_in[0];
    const int*   ei   = (const int*)d_in[1];
    const float* Wq   = (const float*)d_in[3];
    const float* bq   = (const float*)d_in[4];
    const float* Wk   = (const float*)d_in[5];
    const float* bk   = (const float*)d_in[6];
    const float* Wv   = (const float*)d_in[7];
    const float* bv   = (const float*)d_in[8];
    const float* Wsk  = (const float*)d_in[9];
    const float* bsk  = (const float*)d_in[10];
    const float* Wout = (const float*)d_in[11];
    const float* bout = (const float*)d_in[12];

    const int* srcv = ei;        // edge_index[0]
    const int* dstv = ei + EE;   // edge_index[1]

    float *pq, *pk, *pv, *ps, *px0, *px1;
    cudaGetSymbolAddress((void**)&pq,  g_q);
    cudaGetSymbolAddress((void**)&pk,  g_k);
    cudaGetSymbolAddress((void**)&pv,  g_v);
    cudaGetSymbolAddress((void**)&ps,  g_s);
    cudaGetSymbolAddress((void**)&px0, g_x0);
    cudaGetSymbolAddress((void**)&px1, g_x1);

    // ---- CSR build ----
    k_zero_cnt<<<(NN + 255) / 256, 256>>>();
    k_hist<<<(EE + 255) / 256, 256>>>(dstv);
    int nb = (NN + 1023) / 1024;   // 49
    k_scan1<<<nb, 1024>>>();
    k_scan2<<<1, 64>>>(nb);
    k_scan3<<<nb, 1024>>>();
    k_scatter<<<(EE + 255) / 256, 256>>>(srcv, dstv);

    // ---- layers ----
    int rowTiles = (NN + 127) / 128;          // 391
    int attnBlocks = (NN + 7) / 8;            // 8 warps / block
    const float* xin = x;
    float* bufs[2] = {px0, px1};
    for (int l = 0; l < LL; l++) {
        const float* wq = Wq + (size_t)l * 128 * 128;
        const float* wk = Wk + (size_t)l * 128 * 128;
        const float* wv = Wv + (size_t)l * 128 * 128;
        const float* ws = Wsk + (size_t)l * 128 * 128;
        gemmQKVS<<<dim3(rowTiles, 4), 256>>>(xin,
            wq, wk, wv, ws,
            bq + l * 128, bk + l * 128, bv + l * 128, bsk + l * 128,
            pq, pk, pv, ps, NN);
        float* xo = bufs[l & 1];
        attn<<<attnBlocks, 256>>>(pq, pk, pv, ps, xo);
        xin = xo;
    }

    // ---- final linear ----
    gemmQKVS<<<dim3(rowTiles, 1), 256>>>(xin,
        Wout, Wout, Wout, Wout,
        bout, bout, bout, bout,
        (float*)d_out, (float*)d_out, (float*)d_out, (float*)d_out, NN);
}

// round 3
// speedup vs baseline: 2.3206x; 1.7244x over previous
#include <cuda_runtime.h>
#include <cuda_bf16.h>
#include <cstdint>

#define NN 50000
#define EE 800000
#define DD 128
#define HH 8
#define CC 16
#define LL 4

// ---------------- device scratch (static: allocation-free rule) ----------------
__device__ float g_q[NN * DD];
__device__ float g_k[NN * DD];
__device__ float g_v[NN * DD];
__device__ float g_s[NN * DD];
__device__ __nv_bfloat16 g_xh[NN * DD];
__device__ __nv_bfloat16 g_xl[NN * DD];
__device__ __nv_bfloat16 g_Wh[17 * DD * DD];
__device__ __nv_bfloat16 g_Wl[17 * DD * DD];
__device__ int   g_cnt[NN];
__device__ int   g_off[NN + 1];
__device__ int   g_cur[NN];
__device__ int   g_src[EE];
__device__ int   g_part[64];

// ---------------- CSR build ----------------
__global__ void k_zero_cnt() {
    int i = blockIdx.x * blockDim.x + threadIdx.x;
    if (i < NN) g_cnt[i] = 0;
}

__global__ void k_hist(const int* __restrict__ dst) {
    int e = blockIdx.x * blockDim.x + threadIdx.x;
    if (e < EE) atomicAdd(&g_cnt[dst[e]], 1);
}

__global__ void k_scan1() {
    __shared__ int sm[1024];
    int tid = threadIdx.x;
    int i = blockIdx.x * 1024 + tid;
    int vin = (i < NN) ? g_cnt[i] : 0;
    sm[tid] = vin;
    __syncthreads();
#pragma unroll
    for (int o = 1; o < 1024; o <<= 1) {
        int t = (tid >= o) ? sm[tid - o] : 0;
        __syncthreads();
        sm[tid] += t;
        __syncthreads();
    }
    if (i < NN) g_off[i] = sm[tid] - vin;
    if (tid == 1023) g_part[blockIdx.x] = sm[1023];
}

__global__ void k_scan2(int nb) {
    __shared__ int sm[64];
    int tid = threadIdx.x;
    int v = (tid < nb) ? g_part[tid] : 0;
    sm[tid] = v;
    __syncthreads();
#pragma unroll
    for (int o = 1; o < 64; o <<= 1) {
        int t = (tid >= o) ? sm[tid - o] : 0;
        __syncthreads();
        sm[tid] += t;
        __syncthreads();
    }
    if (tid < nb) g_part[tid] = sm[tid] - v;
}

__global__ void k_scan3() {
    int i = blockIdx.x * 1024 + threadIdx.x;
    if (i < NN) {
        int o = g_off[i] + g_part[blockIdx.x];
        g_off[i] = o;
        g_cur[i] = o;
    }
    if (i == 0) g_off[NN] = EE;
}

__global__ void k_scatter(const int* __restrict__ src, const int* __restrict__ dst) {
    int e = blockIdx.x * blockDim.x + threadIdx.x;
    if (e < EE) {
        int d = dst[e];
        int p = atomicAdd(&g_cur[d], 1);
        g_src[p] = src[e];
    }
}

// ---------------- split conversions ----------------
__global__ void k_splitX(const float* __restrict__ x) {
    int i = blockIdx.x * blockDim.x + threadIdx.x;
    if (i < NN * DD) {
        float v = x[i];
        __nv_bfloat16 h = __float2bfloat16(v);
        g_xh[i] = h;
        g_xl[i] = __float2bfloat16(v - __bfloat162float(h));
    }
}

__global__ void k_splitW(const float* __restrict__ Wq, const float* __restrict__ Wk,
                         const float* __restrict__ Wv, const float* __restrict__ Ws,
                         const float* __restrict__ Wo) {
    int i = blockIdx.x * blockDim.x + threadIdx.x;
    if (i >= 17 * DD * DD) return;
    int mat = i >> 14;
    int off = i & 16383;
    float v;
    if (mat == 16) v = Wo[off];
    else {
        int l = mat >> 2, m = mat & 3;
        const float* s = (m == 0) ? Wq : (m == 1) ? Wk : (m == 2) ? Wv : Ws;
        v = s[l * 16384 + off];
    }
    __nv_bfloat16 h = __float2bfloat16(v);
    g_Wh[i] = h;
    g_Wl[i] = __float2bfloat16(v - __bfloat162float(h));
}

// ---------------- tensor-core helpers ----------------
__device__ __forceinline__ unsigned smem_u32(const void* p) {
    return (unsigned)__cvta_generic_to_shared(p);
}
__device__ __forceinline__ void ldsm4(unsigned r[4], unsigned addr) {
    asm volatile("ldmatrix.sync.aligned.m8n8.x4.shared.b16 {%0,%1,%2,%3}, [%4];"
                 : "=r"(r[0]), "=r"(r[1]), "=r"(r[2]), "=r"(r[3]) : "r"(addr));
}
__device__ __forceinline__ void ldsm4t(unsigned* r, unsigned addr) {
    asm volatile("ldmatrix.sync.aligned.m8n8.x4.trans.shared.b16 {%0,%1,%2,%3}, [%4];"
                 : "=r"(r[0]), "=r"(r[1]), "=r"(r[2]), "=r"(r[3]) : "r"(addr));
}
__device__ __forceinline__ void mma_bf16(float d[4], const unsigned a[4],
                                         unsigned b0, unsigned b1) {
    asm volatile(
        "mma.sync.aligned.m16n8k16.row.col.f32.bf16.bf16.f32 "
        "{%0,%1,%2,%3},{%4,%5,%6,%7},{%8,%9},{%0,%1,%2,%3};"
        : "+f"(d[0]), "+f"(d[1]), "+f"(d[2]), "+f"(d[3])
        : "r"(a[0]), "r"(a[1]), "r"(a[2]), "r"(a[3]), "r"(b0), "r"(b1));
}
__device__ __forceinline__ void cpa16(unsigned dst, const void* src, int sz) {
    asm volatile("cp.async.cg.shared.global [%0], [%1], 16, %2;"
                 :: "r"(dst), "l"(src), "r"(sz) : "memory");
}

// ---------------- tensor-core GEMM: out[M,128] = (xh+xl)@(Wh+Wl) + bias ----------------
// grid.x = 128-row tiles, grid.y selects matrix (mat id / bias / out)
__global__ void __launch_bounds__(256, 1)
gemmTC(int mat0, int mat1, int mat2, int mat3,
       const float* __restrict__ b0p, const float* __restrict__ b1p,
       const float* __restrict__ b2p, const float* __restrict__ b3p,
       float* __restrict__ o0, float* __restrict__ o1,
       float* __restrict__ o2, float* __restrict__ o3, int M) {
    int matId; const float* bias; float* out;
    switch (blockIdx.y) {
        case 0: matId = mat0; bias = b0p; out = o0; break;
        case 1: matId = mat1; bias = b1p; out = o1; break;
        case 2: matId = mat2; bias = b2p; out = o2; break;
        default: matId = mat3; bias = b3p; out = o3; break;
    }
    const __nv_bfloat16* __restrict__ Wh = g_Wh + (size_t)matId * 16384;
    const __nv_bfloat16* __restrict__ Wl = g_Wl + (size_t)matId * 16384;

    extern __shared__ __nv_bfloat16 smB[];
    __nv_bfloat16* sAh = smB;              // 2 stages x 128x64
    __nv_bfloat16* sAl = smB + 16384;
    __nv_bfloat16* sWh = smB + 32768;      // 2 stages x 64x128
    __nv_bfloat16* sWl = smB + 49152;

    const int tid = threadIdx.x;
    const int m0 = blockIdx.x * 128;

    // issue cp.async for both K-halves
#pragma unroll
    for (int s = 0; s < 2; s++) {
        int kb = s * 64;
#pragma unroll
        for (int i = 0; i < 4; i++) {
            int q = tid * 4 + i;
            int row = q >> 3, c = q & 7;
            int gr = m0 + row;
            int sz = (gr < M) ? 16 : 0;
            unsigned doff = row * 64 + ((c ^ (row & 7)) * 8);
            cpa16(smem_u32(sAh + s * 8192 + doff), g_xh + (size_t)gr * 128 + kb + c * 8, sz);
            cpa16(smem_u32(sAl + s * 8192 + doff), g_xl + (size_t)gr * 128 + kb + c * 8, sz);
        }
#pragma unroll
        for (int i = 0; i < 4; i++) {
            int q = tid * 4 + i;
            int row = q >> 4, c = q & 15;
            unsigned doff = row * 128 + ((c ^ (row & 7)) * 8);
            cpa16(smem_u32(sWh + s * 8192 + doff), Wh + (size_t)(kb + row) * 128 + c * 8, 16);
            cpa16(smem_u32(sWl + s * 8192 + doff), Wl + (size_t)(kb + row) * 128 + c * 8, 16);
        }
        asm volatile("cp.async.commit_group;" ::: "memory");
    }

    const int lane = tid & 31, warp = tid >> 5;
    const int wm = (warp & 3) * 32;        // warp row base
    const int wn = (warp >> 2) * 64;       // warp col base
    const int lsw = lane & 7;
    const int hi8 = (lane >> 4) & 1;
    const unsigned rb0 = (unsigned)((wm + (lane & 15)) * 128);
    const unsigned rb1 = rb0 + 2048;       // +16 rows
    const unsigned kn = (unsigned)((lane & 15) * 256);

    float d[2][8][4];
#pragma unroll
    for (int t = 0; t < 2; t++)
#pragma unroll
        for (int j = 0; j < 8; j++)
#pragma unroll
            for (int c = 0; c < 4; c++) d[t][j][c] = 0.f;

#pragma unroll
    for (int s = 0; s < 2; s++) {
        if (s == 0) { asm volatile("cp.async.wait_group 1;" ::: "memory"); }
        else        { asm volatile("cp.async.wait_group 0;" ::: "memory"); }
        __syncthreads();
        unsigned uAh = smem_u32(sAh + s * 8192);
        unsigned uAl = smem_u32(sAl + s * 8192);
        unsigned uWh = smem_u32(sWh + s * 8192);
        unsigned uWl = smem_u32(sWl + s * 8192);

#pragma unroll
        for (int kk = 0; kk < 4; kk++) {
            unsigned asw = (unsigned)((((kk * 2 + hi8) ^ lsw)) * 16);
            unsigned ah0[4], ah1[4], al0[4], al1[4];
            ldsm4(ah0, uAh + rb0 + asw);
            ldsm4(ah1, uAh + rb1 + asw);
            ldsm4(al0, uAl + rb0 + asw);
            ldsm4(al1, uAl + rb1 + asw);

            unsigned bh[16], bl[16];
#pragma unroll
            for (int g = 0; g < 4; g++) {
                unsigned cg = (unsigned)((wn >> 3) + g * 2 + hi8);
                unsigned ba = kn + ((cg ^ (unsigned)lsw) * 16) + (unsigned)kk * 4096;
                ldsm4t(&bh[g * 4], uWh + ba);
                ldsm4t(&bl[g * 4], uWl + ba);
            }
#pragma unroll
            for (int j = 0; j < 8; j++) {
                int bi = (j >> 1) * 4 + (j & 1) * 2;
                unsigned h0 = bh[bi], h1 = bh[bi + 1];
                unsigned l0 = bl[bi], l1 = bl[bi + 1];
                mma_bf16(d[0][j], ah0, h0, h1);
                mma_bf16(d[1][j], ah1, h0, h1);
                mma_bf16(d[0][j], al0, h0, h1);
                mma_bf16(d[1][j], al1, h0, h1);
                mma_bf16(d[0][j], ah0, l0, l1);
                mma_bf16(d[1][j], ah1, l0, l1);
            }
        }
        if (s == 0) __syncthreads();   // buffers distinct, but keep store order clean
    }

    // epilogue: add bias, store fp32
    const int r = lane >> 2, cp2 = (lane & 3) * 2;
#pragma unroll
    for (int t = 0; t < 2; t++) {
        int R0 = m0 + wm + t * 16 + r;
#pragma unroll
        for (int j = 0; j < 8; j++) {
            int C = wn + j * 8 + cp2;
            float2 bb = *(const float2*)(bias + C);
            if (R0 < M) {
                float2 u = {d[t][j][0] + bb.x, d[t][j][1] + bb.y};
                *(float2*)(out + (size_t)R0 * 128 + C) = u;
            }
            int R1 = R0 + 8;
            if (R1 < M) {
                float2 u = {d[t][j][2] + bb.x, d[t][j][3] + bb.y};
                *(float2*)(out + (size_t)R1 * 128 + C) = u;
            }
        }
    }
}

// ---------------- attention: warp per dst node, online softmax ----------------
// epilogue writes next-layer input as bf16 hi/lo split
__global__ void attn(const float* __restrict__ q, const float* __restrict__ k,
                     const float* __restrict__ v, const float* __restrict__ skip) {
    int warp = (blockIdx.x * blockDim.x + threadIdx.x) >> 5;
    if (warp >= NN) return;
    int lane = threadIdx.x & 31;
    int col  = (lane >> 2) * 16 + (lane & 3) * 4;   // head*16 + chunk*4

    float4 q4 = *(const float4*)(q + (size_t)warp * 128 + col);
    float m = -1e30f, z = 0.f;
    float4 acc = {0.f, 0.f, 0.f, 0.f};

    int beg = g_off[warp], end = g_off[warp + 1];
    for (int base = beg; base < end; base += 32) {
        int mye = base + lane;
        int sreg = (mye < end) ? g_src[mye] : 0;
        int cnt = min(32, end - base);
        for (int i = 0; i < cnt; i++) {
            int sn = __shfl_sync(0xffffffffu, sreg, i);
            const float4 k4 = *(const float4*)(k + (size_t)sn * 128 + col);
            float dd = q4.x * k4.x + q4.y * k4.y + q4.z * k4.z + q4.w * k4.w;
            dd += __shfl_xor_sync(0xffffffffu, dd, 1);
            dd += __shfl_xor_sync(0xffffffffu, dd, 2);
            dd *= 0.25f;   // 1/sqrt(16)
            const float4 v4 = *(const float4*)(v + (size_t)sn * 128 + col);
            if (dd > m) {
                float sc = __expf(m - dd);
                z *= sc; acc.x *= sc; acc.y *= sc; acc.z *= sc; acc.w *= sc;
                m = dd;
            }
            float p = __expf(dd - m);
            z += p;
            acc.x += p * v4.x; acc.y += p * v4.y; acc.z += p * v4.z; acc.w += p * v4.w;
        }
    }

    float inv = (z > 0.f) ? 1.f / z : 0.f;
    float4 sk = *(const float4*)(skip + (size_t)warp * 128 + col);
    float ox = fmaxf(acc.x * inv + sk.x, 0.f);
    float oy = fmaxf(acc.y * inv + sk.y, 0.f);
    float oz = fmaxf(acc.z * inv + sk.z, 0.f);
    float ow = fmaxf(acc.w * inv + sk.w, 0.f);

    size_t base = (size_t)warp * 128 + col;
    __nv_bfloat16 hx = __float2bfloat16(ox), hy = __float2bfloat16(oy);
    __nv_bfloat16 hz = __float2bfloat16(oz), hw = __float2bfloat16(ow);
    __nv_bfloat162 hh0; hh0.x = hx; hh0.y = hy;
    __nv_bfloat162 hh1; hh1.x = hz; hh1.y = hw;
    *(__nv_bfloat162*)(g_xh + base)     = hh0;
    *(__nv_bfloat162*)(g_xh + base + 2) = hh1;
    __nv_bfloat162 ll0, ll1;
    ll0.x = __float2bfloat16(ox - __bfloat162float(hx));
    ll0.y = __float2bfloat16(oy - __bfloat162float(hy));
    ll1.x = __float2bfloat16(oz - __bfloat162float(hz));
    ll1.y = __float2bfloat16(ow - __bfloat162float(hw));
    *(__nv_bfloat162*)(g_xl + base)     = ll0;
    *(__nv_bfloat162*)(g_xl + base + 2) = ll1;
}

// ---------------- launch ----------------
extern "C" void kernel_launch(void* const* d_in, const int* in_sizes, int n_in,
                              void* d_out, int out_size) {
    const float* x    = (const float*)d_in[0];
    const int*   ei   = (const int*)d_in[1];
    const float* Wq   = (const float*)d_in[3];
    const float* bq   = (const float*)d_in[4];
    const float* Wk   = (const float*)d_in[5];
    const float* bk   = (const float*)d_in[6];
    const float* Wv   = (const float*)d_in[7];
    const float* bv   = (const float*)d_in[8];
    const float* Wsk  = (const float*)d_in[9];
    const float* bsk  = (const float*)d_in[10];
    const float* Wout = (const float*)d_in[11];
    const float* bout = (const float*)d_in[12];

    const int* srcv = ei;
    const int* dstv = ei + EE;

    float *pq, *pk, *pv, *ps;
    cudaGetSymbolAddress((void**)&pq, g_q);
    cudaGetSymbolAddress((void**)&pk, g_k);
    cudaGetSymbolAddress((void**)&pv, g_v);
    cudaGetSymbolAddress((void**)&ps, g_s);

    cudaFuncSetAttribute(gemmTC, cudaFuncAttributeMaxDynamicSharedMemorySize, 131072);

    // ---- splits + CSR build ----
    k_splitX<<<(NN * DD + 255) / 256, 256>>>(x);
    k_splitW<<<(17 * DD * DD + 255) / 256, 256>>>(Wq, Wk, Wv, Wsk, Wout);
    k_zero_cnt<<<(NN + 255) / 256, 256>>>();
    k_hist<<<(EE + 255) / 256, 256>>>(dstv);
    int nb = (NN + 1023) / 1024;
    k_scan1<<<nb, 1024>>>();
    k_scan2<<<1, 64>>>(nb);
    k_scan3<<<nb, 1024>>>();
    k_scatter<<<(EE + 255) / 256, 256>>>(srcv, dstv);

    // ---- layers ----
    int rowTiles = (NN + 127) / 128;          // 391
    int attnBlocks = (NN + 7) / 8;
    for (int l = 0; l < LL; l++) {
        gemmTC<<<dim3(rowTiles, 4), 256, 131072>>>(
            l * 4 + 0, l * 4 + 1, l * 4 + 2, l * 4 + 3,
            bq + l * 128, bk + l * 128, bv + l * 128, bsk + l * 128,
            pq, pk, pv, ps, NN);
        attn<<<attnBlocks, 256>>>(pq, pk, pv, ps);
    }

    // ---- final linear ----
    gemmTC<<<dim3(rowTiles, 1), 256, 131072>>>(
        16, 16, 16, 16,
        bout, bout, bout, bout,
        (float*)d_out, (float*)d_out, (float*)d_out, (float*)d_out, NN);
}

// round 5
// speedup vs baseline: 2.5265x; 1.0887x over previous
#include <cuda_runtime.h>
#include <cuda_bf16.h>
#include <cstdint>

#define NN 50000
#define EE 800000
#define DD 128
#define HH 8
#define CC 16
#define LL 4

// ---------------- device scratch (static: allocation-free rule) ----------------
__device__ float g_q[NN * DD];
__device__ float g_k[NN * DD];
__device__ float g_v[NN * DD];
__device__ float g_s[NN * DD];
__device__ __nv_bfloat16 g_xh[NN * DD];
__device__ __nv_bfloat16 g_xl[NN * DD];
__device__ __nv_bfloat16 g_Wh[17 * DD * DD];
__device__ __nv_bfloat16 g_Wl[17 * DD * DD];
__device__ int   g_cnt[NN];
__device__ int   g_off[NN + 1];
__device__ int   g_cur[NN];
__device__ int   g_src[EE];
__device__ int   g_part[64];

// ---------------- CSR build ----------------
__global__ void k_zero_cnt() {
    int i = blockIdx.x * blockDim.x + threadIdx.x;
    if (i < NN) g_cnt[i] = 0;
}

__global__ void k_hist(const int* __restrict__ dst) {
    int e = blockIdx.x * blockDim.x + threadIdx.x;
    if (e < EE) atomicAdd(&g_cnt[dst[e]], 1);
}

__global__ void k_scan1() {
    __shared__ int sm[1024];
    int tid = threadIdx.x;
    int i = blockIdx.x * 1024 + tid;
    int vin = (i < NN) ? g_cnt[i] : 0;
    sm[tid] = vin;
    __syncthreads();
#pragma unroll
    for (int o = 1; o < 1024; o <<= 1) {
        int t = (tid >= o) ? sm[tid - o] : 0;
        __syncthreads();
        sm[tid] += t;
        __syncthreads();
    }
    if (i < NN) g_off[i] = sm[tid] - vin;
    if (tid == 1023) g_part[blockIdx.x] = sm[1023];
}

__global__ void k_scan2(int nb) {
    __shared__ int sm[64];
    int tid = threadIdx.x;
    int v = (tid < nb) ? g_part[tid] : 0;
    sm[tid] = v;
    __syncthreads();
#pragma unroll
    for (int o = 1; o < 64; o <<= 1) {
        int t = (tid >= o) ? sm[tid - o] : 0;
        __syncthreads();
        sm[tid] += t;
        __syncthreads();
    }
    if (tid < nb) g_part[tid] = sm[tid] - v;
}

__global__ void k_scan3() {
    int i = blockIdx.x * 1024 + threadIdx.x;
    if (i < NN) {
        int o = g_off[i] + g_part[blockIdx.x];
        g_off[i] = o;
        g_cur[i] = o;
    }
    if (i == 0) g_off[NN] = EE;
}

__global__ void k_scatter(const int* __restrict__ src, const int* __restrict__ dst) {
    int e = blockIdx.x * blockDim.x + threadIdx.x;
    if (e < EE) {
        int d = dst[e];
        int p = atomicAdd(&g_cur[d], 1);
        g_src[p] = src[e];
    }
}

// ---------------- split conversions ----------------
__global__ void k_splitX(const float* __restrict__ x) {
    int i = blockIdx.x * blockDim.x + threadIdx.x;
    if (i < NN * DD) {
        float v = x[i];
        __nv_bfloat16 h = __float2bfloat16(v);
        g_xh[i] = h;
        g_xl[i] = __float2bfloat16(v - __bfloat162float(h));
    }
}

__global__ void k_splitW(const float* __restrict__ Wq, const float* __restrict__ Wk,
                         const float* __restrict__ Wv, const float* __restrict__ Ws,
                         const float* __restrict__ Wo) {
    int i = blockIdx.x * blockDim.x + threadIdx.x;
    if (i >= 17 * DD * DD) return;
    int mat = i >> 14;
    int off = i & 16383;
    float v;
    if (mat == 16) v = Wo[off];
    else {
        int l = mat >> 2, m = mat & 3;
        const float* s = (m == 0) ? Wq : (m == 1) ? Wk : (m == 2) ? Wv : Ws;
        v = s[l * 16384 + off];
    }
    __nv_bfloat16 h = __float2bfloat16(v);
    g_Wh[i] = h;
    g_Wl[i] = __float2bfloat16(v - __bfloat162float(h));
}

// ---------------- tensor-core helpers ----------------
__device__ __forceinline__ unsigned smem_u32(const void* p) {
    return (unsigned)__cvta_generic_to_shared(p);
}
__device__ __forceinline__ void ldsm4(unsigned r[4], unsigned addr) {
    asm volatile("ldmatrix.sync.aligned.m8n8.x4.shared.b16 {%0,%1,%2,%3}, [%4];"
                 : "=r"(r[0]), "=r"(r[1]), "=r"(r[2]), "=r"(r[3]) : "r"(addr));
}
__device__ __forceinline__ void ldsm4t(unsigned* r, unsigned addr) {
    asm volatile("ldmatrix.sync.aligned.m8n8.x4.trans.shared.b16 {%0,%1,%2,%3}, [%4];"
                 : "=r"(r[0]), "=r"(r[1]), "=r"(r[2]), "=r"(r[3]) : "r"(addr));
}
__device__ __forceinline__ void mma_bf16(float d[4], const unsigned a[4],
                                         unsigned b0, unsigned b1) {
    asm volatile(
        "mma.sync.aligned.m16n8k16.row.col.f32.bf16.bf16.f32 "
        "{%0,%1,%2,%3},{%4,%5,%6,%7},{%8,%9},{%0,%1,%2,%3};"
        : "+f"(d[0]), "+f"(d[1]), "+f"(d[2]), "+f"(d[3])
        : "r"(a[0]), "r"(a[1]), "r"(a[2]), "r"(a[3]), "r"(b0), "r"(b1));
}
__device__ __forceinline__ void cpa16(unsigned dst, const void* src, int sz) {
    asm volatile("cp.async.cg.shared.global [%0], [%1], 16, %2;"
                 :: "r"(dst), "l"(src), "r"(sz) : "memory");
}

// ---------------- tensor-core GEMM: out[M,128] = (xh+xl)@(Wh+Wl) + bias ----------------
__global__ void __launch_bounds__(256, 1)
gemmTC(int mat0, int mat1, int mat2, int mat3,
       const float* __restrict__ b0p, const float* __restrict__ b1p,
       const float* __restrict__ b2p, const float* __restrict__ b3p,
       float* __restrict__ o0, float* __restrict__ o1,
       float* __restrict__ o2, float* __restrict__ o3, int M) {
    int matId; const float* bias; float* out;
    switch (blockIdx.y) {
        case 0: matId = mat0; bias = b0p; out = o0; break;
        case 1: matId = mat1; bias = b1p; out = o1; break;
        case 2: matId = mat2; bias = b2p; out = o2; break;
        default: matId = mat3; bias = b3p; out = o3; break;
    }
    const __nv_bfloat16* __restrict__ Wh = g_Wh + (size_t)matId * 16384;
    const __nv_bfloat16* __restrict__ Wl = g_Wl + (size_t)matId * 16384;

    extern __shared__ __nv_bfloat16 smB[];
    __nv_bfloat16* sAh = smB;              // 2 stages x 128x64
    __nv_bfloat16* sAl = smB + 16384;
    __nv_bfloat16* sWh = smB + 32768;      // 2 stages x 64x128
    __nv_bfloat16* sWl = smB + 49152;

    const int tid = threadIdx.x;
    const int m0 = blockIdx.x * 128;

    // issue cp.async for both K-halves
#pragma unroll
    for (int s = 0; s < 2; s++) {
        int kb = s * 64;
#pragma unroll
        for (int i = 0; i < 4; i++) {
            int q = tid * 4 + i;
            int row = q >> 3, c = q & 7;
            int gr = m0 + row;
            int sz = (gr < M) ? 16 : 0;
            unsigned doff = row * 64 + ((c ^ (row & 7)) * 8);
            cpa16(smem_u32(sAh + s * 8192 + doff), g_xh + (size_t)gr * 128 + kb + c * 8, sz);
            cpa16(smem_u32(sAl + s * 8192 + doff), g_xl + (size_t)gr * 128 + kb + c * 8, sz);
        }
#pragma unroll
        for (int i = 0; i < 4; i++) {
            int q = tid * 4 + i;
            int row = q >> 4, c = q & 15;
            unsigned doff = row * 128 + ((c ^ (row & 7)) * 8);
            cpa16(smem_u32(sWh + s * 8192 + doff), Wh + (size_t)(kb + row) * 128 + c * 8, 16);
            cpa16(smem_u32(sWl + s * 8192 + doff), Wl + (size_t)(kb + row) * 128 + c * 8, 16);
        }
        asm volatile("cp.async.commit_group;" ::: "memory");
    }

    const int lane = tid & 31, warp = tid >> 5;
    const int wm = (warp & 3) * 32;
    const int wn = (warp >> 2) * 64;
    const int lsw = lane & 7;
    const int hi8 = (lane >> 4) & 1;
    const unsigned rb0 = (unsigned)((wm + (lane & 15)) * 128);
    const unsigned rb1 = rb0 + 2048;
    const unsigned kn = (unsigned)((lane & 15) * 256);

    float d[2][8][4];
#pragma unroll
    for (int t = 0; t < 2; t++)
#pragma unroll
        for (int j = 0; j < 8; j++)
#pragma unroll
            for (int c = 0; c < 4; c++) d[t][j][c] = 0.f;

#pragma unroll
    for (int s = 0; s < 2; s++) {
        if (s == 0) { asm volatile("cp.async.wait_group 1;" ::: "memory"); }
        else        { asm volatile("cp.async.wait_group 0;" ::: "memory"); }
        __syncthreads();
        unsigned uAh = smem_u32(sAh + s * 8192);
        unsigned uAl = smem_u32(sAl + s * 8192);
        unsigned uWh = smem_u32(sWh + s * 8192);
        unsigned uWl = smem_u32(sWl + s * 8192);

#pragma unroll
        for (int kk = 0; kk < 4; kk++) {
            unsigned asw = (unsigned)((((kk * 2 + hi8) ^ lsw)) * 16);
            unsigned ah0[4], ah1[4], al0[4], al1[4];
            ldsm4(ah0, uAh + rb0 + asw);
            ldsm4(ah1, uAh + rb1 + asw);
            ldsm4(al0, uAl + rb0 + asw);
            ldsm4(al1, uAl + rb1 + asw);

            unsigned bh[16], bl[16];
#pragma unroll
            for (int g = 0; g < 4; g++) {
                unsigned cg = (unsigned)((wn >> 3) + g * 2 + hi8);
                unsigned ba = kn + ((cg ^ (unsigned)lsw) * 16) + (unsigned)kk * 4096;
                ldsm4t(&bh[g * 4], uWh + ba);
                ldsm4t(&bl[g * 4], uWl + ba);
            }
#pragma unroll
            for (int j = 0; j < 8; j++) {
                int bi = (j >> 1) * 4 + (j & 1) * 2;
                unsigned h0 = bh[bi], h1 = bh[bi + 1];
                unsigned l0 = bl[bi], l1 = bl[bi + 1];
                mma_bf16(d[0][j], ah0, h0, h1);
                mma_bf16(d[1][j], ah1, h0, h1);
                mma_bf16(d[0][j], al0, h0, h1);
                mma_bf16(d[1][j], al1, h0, h1);
                mma_bf16(d[0][j], ah0, l0, l1);
                mma_bf16(d[1][j], ah1, l0, l1);
            }
        }
        if (s == 0) __syncthreads();
    }

    // epilogue: add bias, store fp32
    const int r = lane >> 2, cp2 = (lane & 3) * 2;
#pragma unroll
    for (int t = 0; t < 2; t++) {
        int R0 = m0 + wm + t * 16 + r;
#pragma unroll
        for (int j = 0; j < 8; j++) {
            int C = wn + j * 8 + cp2;
            float2 bb = *(const float2*)(bias + C);
            if (R0 < M) {
                float2 u = {d[t][j][0] + bb.x, d[t][j][1] + bb.y};
                *(float2*)(out + (size_t)R0 * 128 + C) = u;
            }
            int R1 = R0 + 8;
            if (R1 < M) {
                float2 u = {d[t][j][2] + bb.x, d[t][j][3] + bb.y};
                *(float2*)(out + (size_t)R1 * 128 + C) = u;
            }
        }
    }
}

// ---------------- attention: warp per dst node, 2-edge pipelined online softmax ----------------
__global__ void attn(const float* __restrict__ q, const float* __restrict__ k,
                     const float* __restrict__ v, const float* __restrict__ skip) {
    int warp = (blockIdx.x * blockDim.x + threadIdx.x) >> 5;
    if (warp >= NN) return;
    int lane = threadIdx.x & 31;
    int col  = (lane >> 2) * 16 + (lane & 3) * 4;   // head*16 + chunk*4

    float4 q4 = *(const float4*)(q + (size_t)warp * 128 + col);
    float m = -1e30f, z = 0.f;
    float4 acc = {0.f, 0.f, 0.f, 0.f};

    int beg = g_off[warp], end = g_off[warp + 1];
    for (int base = beg; base < end; base += 32) {
        int mye = base + lane;
        int sreg = (mye < end) ? g_src[mye] : 0;
        int cnt = min(32, end - base);
        int i = 0;
        for (; i + 2 <= cnt; i += 2) {
            int s0 = __shfl_sync(0xffffffffu, sreg, i);
            int s1 = __shfl_sync(0xffffffffu, sreg, i + 1);
            const float4 k0 = *(const float4*)(k + (size_t)s0 * 128 + col);
            const float4 k1 = *(const float4*)(k + (size_t)s1 * 128 + col);
            const float4 v0 = *(const float4*)(v + (size_t)s0 * 128 + col);
            const float4 v1 = *(const float4*)(v + (size_t)s1 * 128 + col);
            float d0 = q4.x * k0.x + q4.y * k0.y + q4.z * k0.z + q4.w * k0.w;
            float d1 = q4.x * k1.x + q4.y * k1.y + q4.z * k1.z + q4.w * k1.w;
            d0 += __shfl_xor_sync(0xffffffffu, d0, 1);
            d1 += __shfl_xor_sync(0xffffffffu, d1, 1);
            d0 += __shfl_xor_sync(0xffffffffu, d0, 2);
            d1 += __shfl_xor_sync(0xffffffffu, d1, 2);
            d0 *= 0.25f; d1 *= 0.25f;
            float mn = fmaxf(m, fmaxf(d0, d1));
            float sc = __expf(m - mn);
            float p0 = __expf(d0 - mn);
            float p1 = __expf(d1 - mn);
            z = z * sc + p0 + p1;
            acc.x = acc.x * sc + p0 * v0.x + p1 * v1.x;
            acc.y = acc.y * sc + p0 * v0.y + p1 * v1.y;
            acc.z = acc.z * sc + p0 * v0.z + p1 * v1.z;
            acc.w = acc.w * sc + p0 * v0.w + p1 * v1.w;
            m = mn;
        }
        if (i < cnt) {
            int s0 = __shfl_sync(0xffffffffu, sreg, i);
            const float4 k0 = *(const float4*)(k + (size_t)s0 * 128 + col);
            const float4 v0 = *(const float4*)(v + (size_t)s0 * 128 + col);
            float d0 = q4.x * k0.x + q4.y * k0.y + q4.z * k0.z + q4.w * k0.w;
            d0 += __shfl_xor_sync(0xffffffffu, d0, 1);
            d0 += __shfl_xor_sync(0xffffffffu, d0, 2);
            d0 *= 0.25f;
            float mn = fmaxf(m, d0);
            float sc = __expf(m - mn);
            float p0 = __expf(d0 - mn);
            z = z * sc + p0;
            acc.x = acc.x * sc + p0 * v0.x;
            acc.y = acc.y * sc + p0 * v0.y;
            acc.z = acc.z * sc + p0 * v0.z;
            acc.w = acc.w * sc + p0 * v0.w;
            m = mn;
        }
    }

    float inv = (z > 0.f) ? 1.f / z : 0.f;
    float4 sk = *(const float4*)(skip + (size_t)warp * 128 + col);
    float ox = fmaxf(acc.x * inv + sk.x, 0.f);
    float oy = fmaxf(acc.y * inv + sk.y, 0.f);
    float oz = fmaxf(acc.z * inv + sk.z, 0.f);
    float ow = fmaxf(acc.w * inv + sk.w, 0.f);

    size_t base = (size_t)warp * 128 + col;
    __nv_bfloat16 hx = __float2bfloat16(ox), hy = __float2bfloat16(oy);
    __nv_bfloat16 hz = __float2bfloat16(oz), hw = __float2bfloat16(ow);
    __nv_bfloat162 hh0; hh0.x = hx; hh0.y = hy;
    __nv_bfloat162 hh1; hh1.x = hz; hh1.y = hw;
    *(__nv_bfloat162*)(g_xh + base)     = hh0;
    *(__nv_bfloat162*)(g_xh + base + 2) = hh1;
    __nv_bfloat162 ll0, ll1;
    ll0.x = __float2bfloat16(ox - __bfloat162float(hx));
    ll0.y = __float2bfloat16(oy - __bfloat162float(hy));
    ll1.x = __float2bfloat16(oz - __bfloat162float(hz));
    ll1.y = __float2bfloat16(ow - __bfloat162float(hw));
    *(__nv_bfloat162*)(g_xl + base)     = ll0;
    *(__nv_bfloat162*)(g_xl + base + 2) = ll1;
}

// ---------------- launch ----------------
extern "C" void kernel_launch(void* const* d_in, const int* in_sizes, int n_in,
                              void* d_out, int out_size) {
    const float* x    = (const float*)d_in[0];
    const int*   ei   = (const int*)d_in[1];
    const float* Wq   = (const float*)d_in[3];
    const float* bq   = (const float*)d_in[4];
    const float* Wk   = (const float*)d_in[5];
    const float* bk   = (const float*)d_in[6];
    const float* Wv   = (const float*)d_in[7];
    const float* bv   = (const float*)d_in[8];
    const float* Wsk  = (const float*)d_in[9];
    const float* bsk  = (const float*)d_in[10];
    const float* Wout = (const float*)d_in[11];
    const float* bout = (const float*)d_in[12];

    const int* srcv = ei;
    const int* dstv = ei + EE;

    float *pq, *pk, *pv, *ps;
    cudaGetSymbolAddress((void**)&pq, g_q);
    cudaGetSymbolAddress((void**)&pk, g_k);
    cudaGetSymbolAddress((void**)&pv, g_v);
    cudaGetSymbolAddress((void**)&ps, g_s);

    // one-time resources (no device memory involved)
    static cudaStream_t sSide = nullptr;
    static cudaEvent_t evFork = nullptr, evJoin = nullptr;
    if (!sSide) {
        cudaStreamCreateWithFlags(&sSide, cudaStreamNonBlocking);
        cudaEventCreateWithFlags(&evFork, cudaEventDisableTiming);
        cudaEventCreateWithFlags(&evJoin, cudaEventDisableTiming);
        cudaFuncSetAttribute(gemmTC, cudaFuncAttributeMaxDynamicSharedMemorySize, 131072);
    }

    cudaStream_t s0 = 0;   // legacy default == capture stream context

    int rowTiles = (NN + 127) / 128;
    int attnBlocks = (NN + 7) / 8;
    int nb = (NN + 1023) / 1024;

    // fork: CSR build runs concurrently with splits + layer-0 GEMM
    cudaEventRecord(evFork, s0);
    cudaStreamWaitEvent(sSide, evFork, 0);

    k_zero_cnt<<<(NN + 255) / 256, 256, 0, sSide>>>();
    k_hist<<<(EE + 255) / 256, 256, 0, sSide>>>(dstv);
    k_scan1<<<nb, 1024, 0, sSide>>>();
    k_scan2<<<1, 64, 0, sSide>>>(nb);
    k_scan3<<<nb, 1024, 0, sSide>>>();
    k_scatter<<<(EE + 255) / 256, 256, 0, sSide>>>(srcv, dstv);
    cudaEventRecord(evJoin, sSide);

    k_splitX<<<(NN * DD + 255) / 256, 256, 0, s0>>>(x);
    k_splitW<<<(17 * DD * DD + 255) / 256, 256, 0, s0>>>(Wq, Wk, Wv, Wsk, Wout);

    // layer-0 GEMM needs only the splits
    gemmTC<<<dim3(rowTiles, 4), 256, 131072, s0>>>(
        0, 1, 2, 3, bq, bk, bv, bsk, pq, pk, pv, ps, NN);

    // join: attn needs CSR
    cudaStreamWaitEvent(s0, evJoin, 0);
    attn<<<attnBlocks, 256, 0, s0>>>(pq, pk, pv, ps);

    for (int l = 1; l < LL; l++) {
        gemmTC<<<dim3(rowTiles, 4), 256, 131072, s0>>>(
            l * 4 + 0, l * 4 + 1, l * 4 + 2, l * 4 + 3,
            bq + l * 128, bk + l * 128, bv + l * 128, bsk + l * 128,
            pq, pk, pv, ps, NN);
        attn<<<attnBlocks, 256, 0, s0>>>(pq, pk, pv, ps);
    }

    gemmTC<<<dim3(rowTiles, 1), 256, 131072, s0>>>(
        16, 16, 16, 16, bout, bout, bout, bout,
        (float*)d_out, (float*)d_out, (float*)d_out, (float*)d_out, NN);
}

// round 7
// speedup vs baseline: 2.8648x; 1.1339x over previous
#include <cuda_runtime.h>
#include <cuda_bf16.h>
#include <cstdint>

#define NN 50000
#define EE 800000
#define DD 128
#define HH 8
#define CC 16
#define LL 4

// ---------------- device scratch (static: allocation-free rule) ----------------
__device__ float g_q[NN * DD];
__device__ float g_k[NN * DD];
__device__ float g_v[NN * DD];
__device__ float g_s[NN * DD];
__device__ __nv_bfloat16 g_xh[NN * DD];
__device__ __nv_bfloat16 g_xl[NN * DD];
__device__ __nv_bfloat16 g_Wh[17 * DD * DD];
__device__ __nv_bfloat16 g_Wl[17 * DD * DD];
__device__ int   g_cnt[NN];
__device__ int   g_off[NN + 1];
__device__ int   g_cur[NN];
__device__ int   g_src[EE];
__device__ int   g_part[64];

// ---------------- CSR build ----------------
__global__ void k_zero_cnt() {
    int i = blockIdx.x * blockDim.x + threadIdx.x;
    if (i < NN) g_cnt[i] = 0;
}

__global__ void k_hist(const int* __restrict__ dst) {
    int e = blockIdx.x * blockDim.x + threadIdx.x;
    if (e < EE) atomicAdd(&g_cnt[dst[e]], 1);
}

__global__ void k_scan1() {
    __shared__ int sm[1024];
    int tid = threadIdx.x;
    int i = blockIdx.x * 1024 + tid;
    int vin = (i < NN) ? g_cnt[i] : 0;
    sm[tid] = vin;
    __syncthreads();
#pragma unroll
    for (int o = 1; o < 1024; o <<= 1) {
        int t = (tid >= o) ? sm[tid - o] : 0;
        __syncthreads();
        sm[tid] += t;
        __syncthreads();
    }
    if (i < NN) g_off[i] = sm[tid] - vin;
    if (tid == 1023) g_part[blockIdx.x] = sm[1023];
}

__global__ void k_scan2(int nb) {
    __shared__ int sm[64];
    int tid = threadIdx.x;
    int v = (tid < nb) ? g_part[tid] : 0;
    sm[tid] = v;
    __syncthreads();
#pragma unroll
    for (int o = 1; o < 64; o <<= 1) {
        int t = (tid >= o) ? sm[tid - o] : 0;
        __syncthreads();
        sm[tid] += t;
        __syncthreads();
    }
    if (tid < nb) g_part[tid] = sm[tid] - v;
}

__global__ void k_scan3() {
    int i = blockIdx.x * 1024 + threadIdx.x;
    if (i < NN) {
        int o = g_off[i] + g_part[blockIdx.x];
        g_off[i] = o;
        g_cur[i] = o;
    }
    if (i == 0) g_off[NN] = EE;
}

__global__ void k_scatter(const int* __restrict__ src, const int* __restrict__ dst) {
    int e = blockIdx.x * blockDim.x + threadIdx.x;
    if (e < EE) {
        int d = dst[e];
        int p = atomicAdd(&g_cur[d], 1);
        g_src[p] = src[e];
    }
}

// ---------------- split conversions ----------------
__global__ void k_splitX(const float* __restrict__ x) {
    int i = blockIdx.x * blockDim.x + threadIdx.x;
    if (i < NN * DD) {
        float v = x[i];
        __nv_bfloat16 h = __float2bfloat16(v);
        g_xh[i] = h;
        g_xl[i] = __float2bfloat16(v - __bfloat162float(h));
    }
}

__global__ void k_splitW(const float* __restrict__ Wq, const float* __restrict__ Wk,
                         const float* __restrict__ Wv, const float* __restrict__ Ws,
                         const float* __restrict__ Wo) {
    int i = blockIdx.x * blockDim.x + threadIdx.x;
    if (i >= 17 * DD * DD) return;
    int mat = i >> 14;
    int off = i & 16383;
    float v;
    if (mat == 16) v = Wo[off];
    else {
        int l = mat >> 2, m = mat & 3;
        const float* s = (m == 0) ? Wq : (m == 1) ? Wk : (m == 2) ? Wv : Ws;
        v = s[l * 16384 + off];
    }
    __nv_bfloat16 h = __float2bfloat16(v);
    g_Wh[i] = h;
    g_Wl[i] = __float2bfloat16(v - __bfloat162float(h));
}

// ---------------- tensor-core helpers ----------------
__device__ __forceinline__ unsigned smem_u32(const void* p) {
    return (unsigned)__cvta_generic_to_shared(p);
}
__device__ __forceinline__ void ldsm4(unsigned r[4], unsigned addr) {
    asm volatile("ldmatrix.sync.aligned.m8n8.x4.shared.b16 {%0,%1,%2,%3}, [%4];"
                 : "=r"(r[0]), "=r"(r[1]), "=r"(r[2]), "=r"(r[3]) : "r"(addr));
}
__device__ __forceinline__ void ldsm4t(unsigned* r, unsigned addr) {
    asm volatile("ldmatrix.sync.aligned.m8n8.x4.trans.shared.b16 {%0,%1,%2,%3}, [%4];"
                 : "=r"(r[0]), "=r"(r[1]), "=r"(r[2]), "=r"(r[3]) : "r"(addr));
}
__device__ __forceinline__ void mma_bf16(float d[4], const unsigned a[4],
                                         unsigned b0, unsigned b1) {
    asm volatile(
        "mma.sync.aligned.m16n8k16.row.col.f32.bf16.bf16.f32 "
        "{%0,%1,%2,%3},{%4,%5,%6,%7},{%8,%9},{%0,%1,%2,%3};"
        : "+f"(d[0]), "+f"(d[1]), "+f"(d[2]), "+f"(d[3])
        : "r"(a[0]), "r"(a[1]), "r"(a[2]), "r"(a[3]), "r"(b0), "r"(b1));
}
__device__ __forceinline__ void cpa16(unsigned dst, const void* src, int sz) {
    asm volatile("cp.async.cg.shared.global [%0], [%1], 16, %2;"
                 :: "r"(dst), "l"(src), "r"(sz) : "memory");
}

// ---------------- persistent-W tensor-core GEMM ----------------
// grid = (ctasPerMat, nMat). W (hi+lo) resident in smem; CTA strides over
// 64-row A chunks with double-buffered cp.async.
__global__ void __launch_bounds__(256, 1)
gemmP(int mat0, int mat1, int mat2, int mat3,
      const float* __restrict__ b0p, const float* __restrict__ b1p,
      const float* __restrict__ b2p, const float* __restrict__ b3p,
      float* __restrict__ o0, float* __restrict__ o1,
      float* __restrict__ o2, float* __restrict__ o3, int M) {
    int matId; const float* bias; float* out;
    switch (blockIdx.y) {
        case 0: matId = mat0; bias = b0p; out = o0; break;
        case 1: matId = mat1; bias = b1p; out = o1; break;
        case 2: matId = mat2; bias = b2p; out = o2; break;
        default: matId = mat3; bias = b3p; out = o3; break;
    }
    const __nv_bfloat16* __restrict__ Wh = g_Wh + (size_t)matId * 16384;
    const __nv_bfloat16* __restrict__ Wl = g_Wl + (size_t)matId * 16384;

    extern __shared__ __align__(1024) char smraw[];
    const unsigned uWh = smem_u32(smraw);            // 32 KB: 128 k-rows x 256B
    const unsigned uWl = uWh + 32768;                // 32 KB
    const unsigned uA  = uWh + 65536;                // 2 stages x (hi 16KB + lo 16KB)

    const int tid = threadIdx.x;
    const int lane = tid & 31, warp = tid >> 5;
    const int nChunk = (M + 63) >> 6;
    const int step = gridDim.x;

    // ---- prefetch W (group 0, together with chunk 0) ----
#pragma unroll
    for (int i = 0; i < 8; i++) {
        int q = tid * 8 + i;            // 0..2047
        int row = q >> 4, c = q & 15;
        unsigned doff = (unsigned)(row * 256 + ((c ^ (row & 7)) * 16));
        cpa16(uWh + doff, Wh + row * 128 + c * 8, 16);
        cpa16(uWl + doff, Wl + row * 128 + c * 8, 16);
    }
    // ---- prefetch chunk c0 (stage 0) ----
    int c0 = blockIdx.x;
    {
        int rbase = c0 << 6;
#pragma unroll
        for (int i = 0; i < 4; i++) {
            int q = tid * 4 + i;        // 0..1023
            int row = q >> 4, cc = q & 15;
            int gr = rbase + row;
            int sz = (gr < M) ? 16 : 0;
            unsigned doff = (unsigned)(row * 256 + ((cc ^ (row & 7)) * 16));
            cpa16(uA + doff, g_xh + (size_t)gr * 128 + cc * 8, sz);
            cpa16(uA + 16384 + doff, g_xl + (size_t)gr * 128 + cc * 8, sz);
        }
    }
    asm volatile("cp.async.commit_group;" ::: "memory");
    // ---- prefetch chunk c0+step (stage 1) ----
    if (c0 + step < nChunk) {
        int rbase = (c0 + step) << 6;
#pragma unroll
        for (int i = 0; i < 4; i++) {
            int q = tid * 4 + i;
            int row = q >> 4, cc = q & 15;
            int gr = rbase + row;
            int sz = (gr < M) ? 16 : 0;
            unsigned doff = (unsigned)(row * 256 + ((cc ^ (row & 7)) * 16));
            cpa16(uA + 32768 + doff, g_xh + (size_t)gr * 128 + cc * 8, sz);
            cpa16(uA + 49152 + doff, g_xl + (size_t)gr * 128 + cc * 8, sz);
        }
    }
    asm volatile("cp.async.commit_group;" ::: "memory");

    // warp tile: 32 rows x 32 cols of the 64x128 chunk
    const int wm = (warp & 1) * 32;
    const int wn = (warp >> 1) * 32;
    const int lsw = lane & 7;
    const int hi8 = (lane >> 4) & 1;
    const unsigned rb0 = (unsigned)((wm + (lane & 15)) * 256);
    const unsigned rb1 = rb0 + 4096;
    const unsigned kn = (unsigned)((lane & 15) * 256);

    // bias fragment (per thread: 4 col-pairs)
    const int cp2 = (lane & 3) * 2;
    float2 bb[4];
#pragma unroll
    for (int j = 0; j < 4; j++) bb[j] = *(const float2*)(bias + wn + j * 8 + cp2);
    const int r = lane >> 2;

    int s = 0;
    for (int c = c0; c < nChunk; c += step, s ^= 1) {
        asm volatile("cp.async.wait_group 1;" ::: "memory");
        __syncthreads();

        float d[2][4][4];
#pragma unroll
        for (int t = 0; t < 2; t++)
#pragma unroll
            for (int j = 0; j < 4; j++)
#pragma unroll
                for (int q = 0; q < 4; q++) d[t][j][q] = 0.f;

        unsigned uAh = uA + (unsigned)(s * 32768);
        unsigned uAl = uAh + 16384;

#pragma unroll
        for (int kk = 0; kk < 8; kk++) {
            unsigned asw = (unsigned)(((2 * kk + hi8) ^ lsw) * 16);
            unsigned ah0[4], ah1[4], al0[4], al1[4];
            ldsm4(ah0, uAh + rb0 + asw);
            ldsm4(ah1, uAh + rb1 + asw);
            ldsm4(al0, uAl + rb0 + asw);
            ldsm4(al1, uAl + rb1 + asw);

            unsigned bh[8], bl[8];
#pragma unroll
            for (int g = 0; g < 2; g++) {
                unsigned cg = (unsigned)((wn >> 3) + g * 2 + hi8);
                unsigned ba = kn + ((cg ^ (unsigned)lsw) * 16) + (unsigned)kk * 4096;
                ldsm4t(&bh[g * 4], uWh + ba);
                ldsm4t(&bl[g * 4], uWl + ba);
            }
#pragma unroll
            for (int j = 0; j < 4; j++) {
                int bi = (j >> 1) * 4 + (j & 1) * 2;
                unsigned h0 = bh[bi], h1 = bh[bi + 1];
                unsigned l0 = bl[bi], l1 = bl[bi + 1];
                mma_bf16(d[0][j], ah0, h0, h1);
                mma_bf16(d[1][j], ah1, h0, h1);
                mma_bf16(d[0][j], al0, h0, h1);
                mma_bf16(d[1][j], al1, h0, h1);
                mma_bf16(d[0][j], ah0, l0, l1);
                mma_bf16(d[1][j], ah1, l0, l1);
            }
        }

        // epilogue (registers only -> gmem)
        int rbase = c << 6;
#pragma unroll
        for (int t = 0; t < 2; t++) {
            int R0 = rbase + wm + t * 16 + r;
#pragma unroll
            for (int j = 0; j < 4; j++) {
                int C = wn + j * 8 + cp2;
                if (R0 < M) {
                    float2 u = {d[t][j][0] + bb[j].x, d[t][j][1] + bb[j].y};
                    *(float2*)(out + (size_t)R0 * 128 + C) = u;
                }
                int R1 = R0 + 8;
                if (R1 < M) {
                    float2 u = {d[t][j][2] + bb[j].x, d[t][j][3] + bb[j].y};
                    *(float2*)(out + (size_t)R1 * 128 + C) = u;
                }
            }
        }

        __syncthreads();   // all warps done with stage s before refilling it

        int cn = c + 2 * step;
        if (cn < nChunk) {
            int rb = cn << 6;
            unsigned ubase = uA + (unsigned)(s * 32768);
#pragma unroll
            for (int i = 0; i < 4; i++) {
                int q = tid * 4 + i;
                int row = q >> 4, cc = q & 15;
                int gr = rb + row;
                int sz = (gr < M) ? 16 : 0;
                unsigned doff = (unsigned)(row * 256 + ((cc ^ (row & 7)) * 16));
                cpa16(ubase + doff, g_xh + (size_t)gr * 128 + cc * 8, sz);
                cpa16(ubase + 16384 + doff, g_xl + (size_t)gr * 128 + cc * 8, sz);
            }
        }
        asm volatile("cp.async.commit_group;" ::: "memory");
    }
}

// ---------------- attention: warp per dst node, 2-edge pipelined online softmax ----------------
__global__ void attn(const float* __restrict__ q, const float* __restrict__ k,
                     const float* __restrict__ v, const float* __restrict__ skip) {
    int warp = (blockIdx.x * blockDim.x + threadIdx.x) >> 5;
    if (warp >= NN) return;
    int lane = threadIdx.x & 31;
    int col  = (lane >> 2) * 16 + (lane & 3) * 4;

    float4 q4 = *(const float4*)(q + (size_t)warp * 128 + col);
    float m = -1e30f, z = 0.f;
    float4 acc = {0.f, 0.f, 0.f, 0.f};

    int beg = g_off[warp], end = g_off[warp + 1];
    for (int base = beg; base < end; base += 32) {
        int mye = base + lane;
        int sreg = (mye < end) ? g_src[mye] : 0;
        int cnt = min(32, end - base);
        int i = 0;
        for (; i + 2 <= cnt; i += 2) {
            int s0 = __shfl_sync(0xffffffffu, sreg, i);
            int s1 = __shfl_sync(0xffffffffu, sreg, i + 1);
            const float4 k0 = *(const float4*)(k + (size_t)s0 * 128 + col);
            const float4 k1 = *(const float4*)(k + (size_t)s1 * 128 + col);
            const float4 v0 = *(const float4*)(v + (size_t)s0 * 128 + col);
            const float4 v1 = *(const float4*)(v + (size_t)s1 * 128 + col);
            float d0 = q4.x * k0.x + q4.y * k0.y + q4.z * k0.z + q4.w * k0.w;
            float d1 = q4.x * k1.x + q4.y * k1.y + q4.z * k1.z + q4.w * k1.w;
            d0 += __shfl_xor_sync(0xffffffffu, d0, 1);
            d1 += __shfl_xor_sync(0xffffffffu, d1, 1);
            d0 += __shfl_xor_sync(0xffffffffu, d0, 2);
            d1 += __shfl_xor_sync(0xffffffffu, d1, 2);
            d0 *= 0.25f; d1 *= 0.25f;
            float mn = fmaxf(m, fmaxf(d0, d1));
            float sc = __expf(m - mn);
            float p0 = __expf(d0 - mn);
            float p1 = __expf(d1 - mn);
            z = z * sc + p0 + p1;
            acc.x = acc.x * sc + p0 * v0.x + p1 * v1.x;
            acc.y = acc.y * sc + p0 * v0.y + p1 * v1.y;
            acc.z = acc.z * sc + p0 * v0.z + p1 * v1.z;
            acc.w = acc.w * sc + p0 * v0.w + p1 * v1.w;
            m = mn;
        }
        if (i < cnt) {
            int s0 = __shfl_sync(0xffffffffu, sreg, i);
            const float4 k0 = *(const float4*)(k + (size_t)s0 * 128 + col);
            const float4 v0 = *(const float4*)(v + (size_t)s0 * 128 + col);
            float d0 = q4.x * k0.x + q4.y * k0.y + q4.z * k0.z + q4.w * k0.w;
            d0 += __shfl_xor_sync(0xffffffffu, d0, 1);
            d0 += __shfl_xor_sync(0xffffffffu, d0, 2);
            d0 *= 0.25f;
            float mn = fmaxf(m, d0);
            float sc = __expf(m - mn);
            float p0 = __expf(d0 - mn);
            z = z * sc + p0;
            acc.x = acc.x * sc + p0 * v0.x;
            acc.y = acc.y * sc + p0 * v0.y;
            acc.z = acc.z * sc + p0 * v0.z;
            acc.w = acc.w * sc + p0 * v0.w;
            m = mn;
        }
    }

    float inv = (z > 0.f) ? 1.f / z : 0.f;
    float4 sk = *(const float4*)(skip + (size_t)warp * 128 + col);
    float ox = fmaxf(acc.x * inv + sk.x, 0.f);
    float oy = fmaxf(acc.y * inv + sk.y, 0.f);
    float oz = fmaxf(acc.z * inv + sk.z, 0.f);
    float ow = fmaxf(acc.w * inv + sk.w, 0.f);

    size_t base = (size_t)warp * 128 + col;
    __nv_bfloat16 hx = __float2bfloat16(ox), hy = __float2bfloat16(oy);
    __nv_bfloat16 hz = __float2bfloat16(oz), hw = __float2bfloat16(ow);
    __nv_bfloat162 hh0; hh0.x = hx; hh0.y = hy;
    __nv_bfloat162 hh1; hh1.x = hz; hh1.y = hw;
    *(__nv_bfloat162*)(g_xh + base)     = hh0;
    *(__nv_bfloat162*)(g_xh + base + 2) = hh1;
    __nv_bfloat162 ll0, ll1;
    ll0.x = __float2bfloat16(ox - __bfloat162float(hx));
    ll0.y = __float2bfloat16(oy - __bfloat162float(hy));
    ll1.x = __float2bfloat16(oz - __bfloat162float(hz));
    ll1.y = __float2bfloat16(ow - __bfloat162float(hw));
    *(__nv_bfloat162*)(g_xl + base)     = ll0;
    *(__nv_bfloat162*)(g_xl + base + 2) = ll1;
}

// ---------------- launch ----------------
extern "C" void kernel_launch(void* const* d_in, const int* in_sizes, int n_in,
                              void* d_out, int out_size) {
    const float* x    = (const float*)d_in[0];
    const int*   ei   = (const int*)d_in[1];
    const float* Wq   = (const float*)d_in[3];
    const float* bq   = (const float*)d_in[4];
    const float* Wk   = (const float*)d_in[5];
    const float* bk   = (const float*)d_in[6];
    const float* Wv   = (const float*)d_in[7];
    const float* bv   = (const float*)d_in[8];
    const float* Wsk  = (const float*)d_in[9];
    const float* bsk  = (const float*)d_in[10];
    const float* Wout = (const float*)d_in[11];
    const float* bout = (const float*)d_in[12];

    const int* srcv = ei;
    const int* dstv = ei + EE;

    float *pq, *pk, *pv, *ps;
    cudaGetSymbolAddress((void**)&pq, g_q);
    cudaGetSymbolAddress((void**)&pk, g_k);
    cudaGetSymbolAddress((void**)&pv, g_v);
    cudaGetSymbolAddress((void**)&ps, g_s);

    static cudaStream_t sSide = nullptr;
    static cudaEvent_t evFork = nullptr, evJoin = nullptr;
    if (!sSide) {
        cudaStreamCreateWithFlags(&sSide, cudaStreamNonBlocking);
        cudaEventCreateWithFlags(&evFork, cudaEventDisableTiming);
        cudaEventCreateWithFlags(&evJoin, cudaEventDisableTiming);
        cudaFuncSetAttribute(gemmP, cudaFuncAttributeMaxDynamicSharedMemorySize, 131072);
    }

    cudaStream_t s0 = 0;
    int attnBlocks = (NN + 7) / 8;
    int nb = (NN + 1023) / 1024;

    // fork: CSR build concurrent with splits + layer-0 GEMM
    cudaEventRecord(evFork, s0);
    cudaStreamWaitEvent(sSide, evFork, 0);

    k_zero_cnt<<<(NN + 255) / 256, 256, 0, sSide>>>();
    k_hist<<<(EE + 255) / 256, 256, 0, sSide>>>(dstv);
    k_scan1<<<nb, 1024, 0, sSide>>>();
    k_scan2<<<1, 64, 0, sSide>>>(nb);
    k_scan3<<<nb, 1024, 0, sSide>>>();
    k_scatter<<<(EE + 255) / 256, 256, 0, sSide>>>(srcv, dstv);
    cudaEventRecord(evJoin, sSide);

    k_splitX<<<(NN * DD + 255) / 256, 256, 0, s0>>>(x);
    k_splitW<<<(17 * DD * DD + 255) / 256, 256, 0, s0>>>(Wq, Wk, Wv, Wsk, Wout);

    gemmP<<<dim3(37, 4), 256, 131072, s0>>>(
        0, 1, 2, 3, bq, bk, bv, bsk, pq, pk, pv, ps, NN);

    cudaStreamWaitEvent(s0, evJoin, 0);
    attn<<<attnBlocks, 256, 0, s0>>>(pq, pk, pv, ps);

    for (int l = 1; l < LL; l++) {
        gemmP<<<dim3(37, 4), 256, 131072, s0>>>(
            l * 4 + 0, l * 4 + 1, l * 4 + 2, l * 4 + 3,
            bq + l * 128, bk + l * 128, bv + l * 128, bsk + l * 128,
            pq, pk, pv, ps, NN);
        attn<<<attnBlocks, 256, 0, s0>>>(pq, pk, pv, ps);
    }

    gemmP<<<dim3(148, 1), 256, 131072, s0>>>(
        16, 16, 16, 16, bout, bout, bout, bout,
        (float*)d_out, (float*)d_out, (float*)d_out, (float*)d_out, NN);
}

// round 9
// speedup vs baseline: 2.8798x; 1.0052x over previous
#include <cuda_runtime.h>
#include <cuda_bf16.h>
#include <cstdint>

#define NN 50000
#define EE 800000
#define DD 128
#define HH 8
#define CC 16
#define LL 4

// ---------------- device scratch (static: allocation-free rule) ----------------
__device__ float g_q[NN * DD];
__device__ float g_k[NN * DD];
__device__ __nv_bfloat16 g_vb[NN * DD];        // V in bf16
__device__ float g_s[NN * DD];
__device__ __nv_bfloat16 g_xh[NN * DD];
__device__ __nv_bfloat16 g_xl[NN * DD];
__device__ __nv_bfloat16 g_Wh[17 * DD * DD];
__device__ __nv_bfloat16 g_Wl[17 * DD * DD];
__device__ int   g_cnt[NN];
__device__ int   g_off[NN + 1];
__device__ int   g_cur[NN];
__device__ int   g_src[EE];
__device__ int   g_part[64];

// ---------------- CSR build ----------------
__global__ void k_zero_cnt() {
    int i = blockIdx.x * blockDim.x + threadIdx.x;
    if (i < NN) g_cnt[i] = 0;
}

__global__ void k_hist(const int* __restrict__ dst) {
    int e = blockIdx.x * blockDim.x + threadIdx.x;
    if (e < EE) atomicAdd(&g_cnt[dst[e]], 1);
}

__global__ void k_scan1() {
    __shared__ int sm[1024];
    int tid = threadIdx.x;
    int i = blockIdx.x * 1024 + tid;
    int vin = (i < NN) ? g_cnt[i] : 0;
    sm[tid] = vin;
    __syncthreads();
#pragma unroll
    for (int o = 1; o < 1024; o <<= 1) {
        int t = (tid >= o) ? sm[tid - o] : 0;
        __syncthreads();
        sm[tid] += t;
        __syncthreads();
    }
    if (i < NN) g_off[i] = sm[tid] - vin;
    if (tid == 1023) g_part[blockIdx.x] = sm[1023];
}

__global__ void k_scan2(int nb) {
    __shared__ int sm[64];
    int tid = threadIdx.x;
    int v = (tid < nb) ? g_part[tid] : 0;
    sm[tid] = v;
    __syncthreads();
#pragma unroll
    for (int o = 1; o < 64; o <<= 1) {
        int t = (tid >= o) ? sm[tid - o] : 0;
        __syncthreads();
        sm[tid] += t;
        __syncthreads();
    }
    if (tid < nb) g_part[tid] = sm[tid] - v;
}

__global__ void k_scan3() {
    int i = blockIdx.x * 1024 + threadIdx.x;
    if (i < NN) {
        int o = g_off[i] + g_part[blockIdx.x];
        g_off[i] = o;
        g_cur[i] = o;
    }
    if (i == 0) g_off[NN] = EE;
}

__global__ void k_scatter(const int* __restrict__ src, const int* __restrict__ dst) {
    int e = blockIdx.x * blockDim.x + threadIdx.x;
    if (e < EE) {
        int d = dst[e];
        int p = atomicAdd(&g_cur[d], 1);
        g_src[p] = src[e];
    }
}

// ---------------- split conversions ----------------
__global__ void k_splitX(const float* __restrict__ x) {
    int i = blockIdx.x * blockDim.x + threadIdx.x;
    if (i < NN * DD) {
        float v = x[i];
        __nv_bfloat16 h = __float2bfloat16(v);
        g_xh[i] = h;
        g_xl[i] = __float2bfloat16(v - __bfloat162float(h));
    }
}

__global__ void k_splitW(const float* __restrict__ Wq, const float* __restrict__ Wk,
                         const float* __restrict__ Wv, const float* __restrict__ Ws,
                         const float* __restrict__ Wo) {
    int i = blockIdx.x * blockDim.x + threadIdx.x;
    if (i >= 17 * DD * DD) return;
    int mat = i >> 14;
    int off = i & 16383;
    float v;
    if (mat == 16) v = Wo[off];
    else {
        int l = mat >> 2, m = mat & 3;
        const float* s = (m == 0) ? Wq : (m == 1) ? Wk : (m == 2) ? Wv : Ws;
        v = s[l * 16384 + off];
    }
    __nv_bfloat16 h = __float2bfloat16(v);
    g_Wh[i] = h;
    g_Wl[i] = __float2bfloat16(v - __bfloat162float(h));
}

// ---------------- tensor-core helpers ----------------
__device__ __forceinline__ unsigned smem_u32(const void* p) {
    return (unsigned)__cvta_generic_to_shared(p);
}
__device__ __forceinline__ void ldsm4(unsigned r[4], unsigned addr) {
    asm volatile("ldmatrix.sync.aligned.m8n8.x4.shared.b16 {%0,%1,%2,%3}, [%4];"
                 : "=r"(r[0]), "=r"(r[1]), "=r"(r[2]), "=r"(r[3]) : "r"(addr));
}
__device__ __forceinline__ void ldsm4t(unsigned* r, unsigned addr) {
    asm volatile("ldmatrix.sync.aligned.m8n8.x4.trans.shared.b16 {%0,%1,%2,%3}, [%4];"
                 : "=r"(r[0]), "=r"(r[1]), "=r"(r[2]), "=r"(r[3]) : "r"(addr));
}
__device__ __forceinline__ void mma_bf16(float d[4], const unsigned a[4],
                                         unsigned b0, unsigned b1) {
    asm volatile(
        "mma.sync.aligned.m16n8k16.row.col.f32.bf16.bf16.f32 "
        "{%0,%1,%2,%3},{%4,%5,%6,%7},{%8,%9},{%0,%1,%2,%3};"
        : "+f"(d[0]), "+f"(d[1]), "+f"(d[2]), "+f"(d[3])
        : "r"(a[0]), "r"(a[1]), "r"(a[2]), "r"(a[3]), "r"(b0), "r"(b1));
}
__device__ __forceinline__ void cpa16(unsigned dst, const void* src, int sz) {
    asm volatile("cp.async.cg.shared.global [%0], [%1], 16, %2;"
                 :: "r"(dst), "l"(src), "r"(sz) : "memory");
}

// ---------------- persistent-W tensor-core GEMM ----------------
// grid = (ctasPerMat, nMat). W (hi+lo) resident in smem; CTA strides over
// 64-row A chunks with double-buffered cp.async. bfmask bit y -> bf16 output.
__global__ void __launch_bounds__(256, 1)
gemmP(int mat0, int mat1, int mat2, int mat3,
      const float* __restrict__ b0p, const float* __restrict__ b1p,
      const float* __restrict__ b2p, const float* __restrict__ b3p,
      float* __restrict__ o0, float* __restrict__ o1,
      float* __restrict__ o2, float* __restrict__ o3,
      int M, unsigned bfmask) {
    int matId; const float* bias; float* out;
    switch (blockIdx.y) {
        case 0: matId = mat0; bias = b0p; out = o0; break;
        case 1: matId = mat1; bias = b1p; out = o1; break;
        case 2: matId = mat2; bias = b2p; out = o2; break;
        default: matId = mat3; bias = b3p; out = o3; break;
    }
    const bool obf = (bfmask >> blockIdx.y) & 1u;
    __nv_bfloat16* outb = (__nv_bfloat16*)out;
    const __nv_bfloat16* __restrict__ Wh = g_Wh + (size_t)matId * 16384;
    const __nv_bfloat16* __restrict__ Wl = g_Wl + (size_t)matId * 16384;

    extern __shared__ __align__(1024) char smraw[];
    const unsigned uWh = smem_u32(smraw);            // 32 KB: 128 k-rows x 256B
    const unsigned uWl = uWh + 32768;                // 32 KB
    const unsigned uA  = uWh + 65536;                // 2 stages x (hi 16KB + lo 16KB)

    const int tid = threadIdx.x;
    const int lane = tid & 31, warp = tid >> 5;
    const int nChunk = (M + 63) >> 6;
    const int step = gridDim.x;

    // ---- prefetch W (group 0, together with chunk 0) ----
#pragma unroll
    for (int i = 0; i < 8; i++) {
        int q = tid * 8 + i;            // 0..2047
        int row = q >> 4, c = q & 15;
        unsigned doff = (unsigned)(row * 256 + ((c ^ (row & 7)) * 16));
        cpa16(uWh + doff, Wh + row * 128 + c * 8, 16);
        cpa16(uWl + doff, Wl + row * 128 + c * 8, 16);
    }
    // ---- prefetch chunk c0 (stage 0) ----
    int c0 = blockIdx.x;
    {
        int rbase = c0 << 6;
#pragma unroll
        for (int i = 0; i < 4; i++) {
            int q = tid * 4 + i;        // 0..1023
            int row = q >> 4, cc = q & 15;
            int gr = rbase + row;
            int sz = (gr < M) ? 16 : 0;
            unsigned doff = (unsigned)(row * 256 + ((cc ^ (row & 7)) * 16));
            cpa16(uA + doff, g_xh + (size_t)gr * 128 + cc * 8, sz);
            cpa16(uA + 16384 + doff, g_xl + (size_t)gr * 128 + cc * 8, sz);
        }
    }
    asm volatile("cp.async.commit_group;" ::: "memory");
    // ---- prefetch chunk c0+step (stage 1) ----
    if (c0 + step < nChunk) {
        int rbase = (c0 + step) << 6;
#pragma unroll
        for (int i = 0; i < 4; i++) {
            int q = tid * 4 + i;
            int row = q >> 4, cc = q & 15;
            int gr = rbase + row;
            int sz = (gr < M) ? 16 : 0;
            unsigned doff = (unsigned)(row * 256 + ((cc ^ (row & 7)) * 16));
            cpa16(uA + 32768 + doff, g_xh + (size_t)gr * 128 + cc * 8, sz);
            cpa16(uA + 49152 + doff, g_xl + (size_t)gr * 128 + cc * 8, sz);
        }
    }
    asm volatile("cp.async.commit_group;" ::: "memory");

    // warp tile: 32 rows x 32 cols of the 64x128 chunk
    const int wm = (warp & 1) * 32;
    const int wn = (warp >> 1) * 32;
    const int lsw = lane & 7;
    const int hi8 = (lane >> 4) & 1;
    const unsigned rb0 = (unsigned)((wm + (lane & 15)) * 256);
    const unsigned rb1 = rb0 + 4096;
    const unsigned kn = (unsigned)((lane & 15) * 256);

    // bias fragment (per thread: 4 col-pairs)
    const int cp2 = (lane & 3) * 2;
    float2 bb[4];
#pragma unroll
    for (int j = 0; j < 4; j++) bb[j] = *(const float2*)(bias + wn + j * 8 + cp2);
    const int r = lane >> 2;

    int s = 0;
    for (int c = c0; c < nChunk; c += step, s ^= 1) {
        asm volatile("cp.async.wait_group 1;" ::: "memory");
        __syncthreads();

        float d[2][4][4];
#pragma unroll
        for (int t = 0; t < 2; t++)
#pragma unroll
            for (int j = 0; j < 4; j++)
#pragma unroll
                for (int q = 0; q < 4; q++) d[t][j][q] = 0.f;

        unsigned uAh = uA + (unsigned)(s * 32768);
        unsigned uAl = uAh + 16384;

#pragma unroll
        for (int kk = 0; kk < 8; kk++) {
            unsigned asw = (unsigned)(((2 * kk + hi8) ^ lsw) * 16);
            unsigned ah0[4], ah1[4], al0[4], al1[4];
            ldsm4(ah0, uAh + rb0 + asw);
            ldsm4(ah1, uAh + rb1 + asw);
            ldsm4(al0, uAl + rb0 + asw);
            ldsm4(al1, uAl + rb1 + asw);

            unsigned bh[8], bl[8];
#pragma unroll
            for (int g = 0; g < 2; g++) {
                unsigned cg = (unsigned)((wn >> 3) + g * 2 + hi8);
                unsigned ba = kn + ((cg ^ (unsigned)lsw) * 16) + (unsigned)kk * 4096;
                ldsm4t(&bh[g * 4], uWh + ba);
                ldsm4t(&bl[g * 4], uWl + ba);
            }
#pragma unroll
            for (int j = 0; j < 4; j++) {
                int bi = (j >> 1) * 4 + (j & 1) * 2;
                unsigned h0 = bh[bi], h1 = bh[bi + 1];
                unsigned l0 = bl[bi], l1 = bl[bi + 1];
                mma_bf16(d[0][j], ah0, h0, h1);
                mma_bf16(d[1][j], ah1, h0, h1);
                mma_bf16(d[0][j], al0, h0, h1);
                mma_bf16(d[1][j], al1, h0, h1);
                mma_bf16(d[0][j], ah0, l0, l1);
                mma_bf16(d[1][j], ah1, l0, l1);
            }
        }

        // epilogue (registers only -> gmem)
        int rbase = c << 6;
#pragma unroll
        for (int t = 0; t < 2; t++) {
            int R0 = rbase + wm + t * 16 + r;
#pragma unroll
            for (int j = 0; j < 4; j++) {
                int C = wn + j * 8 + cp2;
                float2 u0 = {d[t][j][0] + bb[j].x, d[t][j][1] + bb[j].y};
                float2 u1 = {d[t][j][2] + bb[j].x, d[t][j][3] + bb[j].y};
                if (obf) {
                    if (R0 < M)
                        *(__nv_bfloat162*)(outb + (size_t)R0 * 128 + C) = __float22bfloat162_rn(u0);
                    if (R0 + 8 < M)
                        *(__nv_bfloat162*)(outb + (size_t)(R0 + 8) * 128 + C) = __float22bfloat162_rn(u1);
                } else {
                    if (R0 < M)
                        *(float2*)(out + (size_t)R0 * 128 + C) = u0;
                    if (R0 + 8 < M)
                        *(float2*)(out + (size_t)(R0 + 8) * 128 + C) = u1;
                }
            }
        }

        __syncthreads();   // all warps done with stage s before refilling it

        int cn = c + 2 * step;
        if (cn < nChunk) {
            int rb = cn << 6;
            unsigned ubase = uA + (unsigned)(s * 32768);
#pragma unroll
            for (int i = 0; i < 4; i++) {
                int q = tid * 4 + i;
                int row = q >> 4, cc = q & 15;
                int gr = rb + row;
                int sz = (gr < M) ? 16 : 0;
                unsigned doff = (unsigned)(row * 256 + ((cc ^ (row & 7)) * 16));
                cpa16(ubase + doff, g_xh + (size_t)gr * 128 + cc * 8, sz);
                cpa16(ubase + 16384 + doff, g_xl + (size_t)gr * 128 + cc * 8, sz);
            }
        }
        asm volatile("cp.async.commit_group;" ::: "memory");
    }
}

// ---------------- attention: warp per dst node, 2-edge pipelined, bf16 V ----------------
__global__ void attn(const float* __restrict__ q, const float* __restrict__ k,
                     const __nv_bfloat16* __restrict__ v, const float* __restrict__ skip) {
    int warp = (blockIdx.x * blockDim.x + threadIdx.x) >> 5;
    if (warp >= NN) return;
    int lane = threadIdx.x & 31;
    int col  = (lane >> 2) * 16 + (lane & 3) * 4;

    float4 q4 = *(const float4*)(q + (size_t)warp * 128 + col);
    float m = -1e30f, z = 0.f;
    float4 acc = {0.f, 0.f, 0.f, 0.f};

    int beg = g_off[warp], end = g_off[warp + 1];
    for (int base = beg; base < end; base += 32) {
        int mye = base + lane;
        int sreg = (mye < end) ? g_src[mye] : 0;
        int cnt = min(32, end - base);
        int i = 0;
        for (; i + 2 <= cnt; i += 2) {
            int s0 = __shfl_sync(0xffffffffu, sreg, i);
            int s1 = __shfl_sync(0xffffffffu, sreg, i + 1);
            const float4 k0 = *(const float4*)(k + (size_t)s0 * 128 + col);
            const float4 k1 = *(const float4*)(k + (size_t)s1 * 128 + col);
            uint2 vr0 = *(const uint2*)(v + (size_t)s0 * 128 + col);
            uint2 vr1 = *(const uint2*)(v + (size_t)s1 * 128 + col);
            float d0 = q4.x * k0.x + q4.y * k0.y + q4.z * k0.z + q4.w * k0.w;
            float d1 = q4.x * k1.x + q4.y * k1.y + q4.z * k1.z + q4.w * k1.w;
            d0 += __shfl_xor_sync(0xffffffffu, d0, 1);
            d1 += __shfl_xor_sync(0xffffffffu, d1, 1);
            d0 += __shfl_xor_sync(0xffffffffu, d0, 2);
            d1 += __shfl_xor_sync(0xffffffffu, d1, 2);
            d0 *= 0.25f; d1 *= 0.25f;
            float2 v0a = __bfloat1622float2(*(const __nv_bfloat162*)&vr0.x);
            float2 v0b = __bfloat1622float2(*(const __nv_bfloat162*)&vr0.y);
            float2 v1a = __bfloat1622float2(*(const __nv_bfloat162*)&vr1.x);
            float2 v1b = __bfloat1622float2(*(const __nv_bfloat162*)&vr1.y);
            float mn = fmaxf(m, fmaxf(d0, d1));
            float sc = __expf(m - mn);
            float p0 = __expf(d0 - mn);
            float p1 = __expf(d1 - mn);
            z = z * sc + p0 + p1;
            acc.x = acc.x * sc + p0 * v0a.x + p1 * v1a.x;
            acc.y = acc.y * sc + p0 * v0a.y + p1 * v1a.y;
            acc.z = acc.z * sc + p0 * v0b.x + p1 * v1b.x;
            acc.w = acc.w * sc + p0 * v0b.y + p1 * v1b.y;
            m = mn;
        }
        if (i < cnt) {
            int s0 = __shfl_sync(0xffffffffu, sreg, i);
            const float4 k0 = *(const float4*)(k + (size_t)s0 * 128 + col);
            uint2 vr0 = *(const uint2*)(v + (size_t)s0 * 128 + col);
            float d0 = q4.x * k0.x + q4.y * k0.y + q4.z * k0.z + q4.w * k0.w;
            d0 += __shfl_xor_sync(0xffffffffu, d0, 1);
            d0 += __shfl_xor_sync(0xffffffffu, d0, 2);
            d0 *= 0.25f;
            float2 v0a = __bfloat1622float2(*(const __nv_bfloat162*)&vr0.x);
            float2 v0b = __bfloat1622float2(*(const __nv_bfloat162*)&vr0.y);
            float mn = fmaxf(m, d0);
            float sc = __expf(m - mn);
            float p0 = __expf(d0 - mn);
            z = z * sc + p0;
            acc.x = acc.x * sc + p0 * v0a.x;
            acc.y = acc.y * sc + p0 * v0a.y;
            acc.z = acc.z * sc + p0 * v0b.x;
            acc.w = acc.w * sc + p0 * v0b.y;
            m = mn;
        }
    }

    float inv = (z > 0.f) ? 1.f / z : 0.f;
    float4 sk = *(const float4*)(skip + (size_t)warp * 128 + col);
    float ox = fmaxf(acc.x * inv + sk.x, 0.f);
    float oy = fmaxf(acc.y * inv + sk.y, 0.f);
    float oz = fmaxf(acc.z * inv + sk.z, 0.f);
    float ow = fmaxf(acc.w * inv + sk.w, 0.f);

    size_t base = (size_t)warp * 128 + col;
    __nv_bfloat16 hx = __float2bfloat16(ox), hy = __float2bfloat16(oy);
    __nv_bfloat16 hz = __float2bfloat16(oz), hw = __float2bfloat16(ow);
    __nv_bfloat162 hh0; hh0.x = hx; hh0.y = hy;
    __nv_bfloat162 hh1; hh1.x = hz; hh1.y = hw;
    *(__nv_bfloat162*)(g_xh + base)     = hh0;
    *(__nv_bfloat162*)(g_xh + base + 2) = hh1;
    __nv_bfloat162 ll0, ll1;
    ll0.x = __float2bfloat16(ox - __bfloat162float(hx));
    ll0.y = __float2bfloat16(oy - __bfloat162float(hy));
    ll1.x = __float2bfloat16(oz - __bfloat162float(hz));
    ll1.y = __float2bfloat16(ow - __bfloat162float(hw));
    *(__nv_bfloat162*)(g_xl + base)     = ll0;
    *(__nv_bfloat162*)(g_xl + base + 2) = ll1;
}

// ---------------- launch ----------------
extern "C" void kernel_launch(void* const* d_in, const int* in_sizes, int n_in,
                              void* d_out, int out_size) {
    const float* x    = (const float*)d_in[0];
    const int*   ei   = (const int*)d_in[1];
    const float* Wq   = (const float*)d_in[3];
    const float* bq   = (const float*)d_in[4];
    const float* Wk   = (const float*)d_in[5];
    const float* bk   = (const float*)d_in[6];
    const float* Wv   = (const float*)d_in[7];
    const float* bv   = (const float*)d_in[8];
    const float* Wsk  = (const float*)d_in[9];
    const float* bsk  = (const float*)d_in[10];
    const float* Wout = (const float*)d_in[11];
    const float* bout = (const float*)d_in[12];

    const int* srcv = ei;
    const int* dstv = ei + EE;

    float *pq, *pk, *ps;
    __nv_bfloat16* pvb;
    cudaGetSymbolAddress((void**)&pq, g_q);
    cudaGetSymbolAddress((void**)&pk, g_k);
    cudaGetSymbolAddress((void**)&pvb, g_vb);
    cudaGetSymbolAddress((void**)&ps, g_s);

    static cudaStream_t sSide = nullptr;
    static cudaEvent_t evFork = nullptr, evJoin = nullptr;
    if (!sSide) {
        cudaStreamCreateWithFlags(&sSide, cudaStreamNonBlocking);
        cudaEventCreateWithFlags(&evFork, cudaEventDisableTiming);
        cudaEventCreateWithFlags(&evJoin, cudaEventDisableTiming);
        cudaFuncSetAttribute(gemmP, cudaFuncAttributeMaxDynamicSharedMemorySize, 131072);
    }

    cudaStream_t s0 = 0;
    int attnBlocks = (NN + 7) / 8;
    int nb = (NN + 1023) / 1024;

    // fork: CSR build concurrent with splits + layer-0 GEMM
    cudaEventRecord(evFork, s0);
    cudaStreamWaitEvent(sSide, evFork, 0);

    k_zero_cnt<<<(NN + 255) / 256, 256, 0, sSide>>>();
    k_hist<<<(EE + 255) / 256, 256, 0, sSide>>>(dstv);
    k_scan1<<<nb, 1024, 0, sSide>>>();
    k_scan2<<<1, 64, 0, sSide>>>(nb);
    k_scan3<<<nb, 1024, 0, sSide>>>();
    k_scatter<<<(EE + 255) / 256, 256, 0, sSide>>>(srcv, dstv);
    cudaEventRecord(evJoin, sSide);

    k_splitX<<<(NN * DD + 255) / 256, 256, 0, s0>>>(x);
    k_splitW<<<(17 * DD * DD + 255) / 256, 256, 0, s0>>>(Wq, Wk, Wv, Wsk, Wout);

    gemmP<<<dim3(37, 4), 256, 131072, s0>>>(
        0, 1, 2, 3, bq, bk, bv, bsk, pq, pk, (float*)pvb, ps, NN, 4u);

    cudaStreamWaitEvent(s0, evJoin, 0);
    attn<<<attnBlocks, 256, 0, s0>>>(pq, pk, pvb, ps);

    for (int l = 1; l < LL; l++) {
        gemmP<<<dim3(37, 4), 256, 131072, s0>>>(
            l * 4 + 0, l * 4 + 1, l * 4 + 2, l * 4 + 3,
            bq + l * 128, bk + l * 128, bv + l * 128, bsk + l * 128,
            pq, pk, (float*)pvb, ps, NN, 4u);
        attn<<<attnBlocks, 256, 0, s0>>>(pq, pk, pvb, ps);
    }

    gemmP<<<dim3(148, 1), 256, 131072, s0>>>(
        16, 16, 16, 16, bout, bout, bout, bout,
        (float*)d_out, (float*)d_out, (float*)d_out, (float*)d_out, NN, 0u);
}